// round 1
// baseline (speedup 1.0000x reference)
#include <cuda_runtime.h>
#include <math.h>

// ---------------- problem constants ----------------
constexpr int Bb   = 2;
constexpr int Ss   = 1024;
constexpr int Dd   = 2048;
constexpr int Hh   = 32;
constexpr int HKV  = 8;
constexpr int HDh  = 64;
constexpr int Ee   = 8;
constexpr int Ii   = 1024;
constexpr int Ttok = Bb * Ss;                 // 2048 tokens
constexpr int QKVW = (Hh + 2 * HKV) * HDh;    // 3072
constexpr int KOFF = Hh * HDh;                // 2048
constexpr int VOFF = (Hh + HKV) * HDh;        // 2560

// ---------------- scratch (device globals; no allocations allowed) ----------------
__device__ float g_h   [(size_t)Ttok * Dd];          // normed activations (h, then g)
__device__ float g_qkv [(size_t)Ttok * QKVW];
__device__ float g_attn[(size_t)Ttok * Dd];
__device__ float g_h1  [(size_t)Ttok * Dd];
__device__ float g_gu  [(size_t)Ee * Ttok * 2048];   // gate|up per expert (slice 0 reused by shared)
__device__ float g_hid [(size_t)Ee * Ttok * 1024];
__device__ int   g_cnt [Ee];
__device__ int   g_idx [Ee * Ttok];
__device__ float g_sc  [Ee * Ttok];

// ---------------- small kernels ----------------
__global__ void zero_cnt_kernel(int* cnt) {
    if (threadIdx.x < Ee) cnt[threadIdx.x] = 0;
}

__global__ void rmsnorm_kernel(const float* __restrict__ x, const float* __restrict__ w,
                               float* __restrict__ out) {
    int row = blockIdx.x;
    const float* xr = x + (size_t)row * Dd;
    float ss = 0.f;
    for (int i = threadIdx.x; i < Dd; i += 256) { float v = xr[i]; ss += v * v; }
    __shared__ float red[256];
    red[threadIdx.x] = ss; __syncthreads();
    for (int s = 128; s > 0; s >>= 1) {
        if (threadIdx.x < s) red[threadIdx.x] += red[threadIdx.x + s];
        __syncthreads();
    }
    float inv = rsqrtf(red[0] / (float)Dd + 1e-5f);
    float* orow = out + (size_t)row * Dd;
    for (int i = threadIdx.x; i < Dd; i += 256) orow[i] = xr[i] * inv * w[i];
}

// rope on q (heads 0..31) and k (heads 32..39) in-place in qkv
__global__ void rope_kernel(float* __restrict__ qkv, const float* __restrict__ cache) {
    int idx = blockIdx.x * blockDim.x + threadIdx.x;
    const int TOT = Ttok * 40 * 32;
    if (idx >= TOT) return;
    int p  = idx & 31;
    int hh = (idx >> 5) % 40;
    int t  = idx / (32 * 40);
    int s  = t % Ss;
    float c  = cache[((size_t)s * 32 + p) * 2 + 0];
    float sn = cache[((size_t)s * 32 + p) * 2 + 1];
    float* base = qkv + (size_t)t * QKVW + hh * 64 + 2 * p;
    float x0 = base[0], x1 = base[1];
    base[0] = x0 * c - x1 * sn;
    base[1] = x1 * c + x0 * sn;
}

// flash attention: grid (S/64, H, B), 64 threads; thread = one query row
__global__ __launch_bounds__(64)
void attn_kernel(const float* __restrict__ qkv, float* __restrict__ out) {
    int qt = blockIdx.x, h = blockIdx.y, b = blockIdx.z;
    int tid = threadIdx.x;
    int qi = qt * 64 + tid;
    int t  = b * Ss + qi;
    int kvh = h >> 2;   // N_REP = 4

    const float* qrow = qkv + (size_t)t * QKVW + h * 64;
    float q[64], acc[64];
#pragma unroll
    for (int d = 0; d < 64; d++) { q[d] = qrow[d]; acc[d] = 0.f; }
    float m = -1e30f, l = 0.f;

    __shared__ float Ks[64][64];
    __shared__ float Vs[64][64];

    int ktiles = qt + 1;
    for (int kt = 0; kt < ktiles; kt++) {
        const float* krow = qkv + (size_t)(b * Ss + kt * 64 + tid) * QKVW + KOFF + kvh * 64;
        const float* vrow = qkv + (size_t)(b * Ss + kt * 64 + tid) * QKVW + VOFF + kvh * 64;
#pragma unroll 8
        for (int d = 0; d < 64; d++) { Ks[tid][d] = krow[d]; Vs[tid][d] = vrow[d]; }
        __syncthreads();
        int kmax = qi - kt * 64 + 1;
        if (kmax > 64) kmax = 64;
        for (int k = 0; k < kmax; k++) {
            float s = 0.f;
#pragma unroll
            for (int d = 0; d < 64; d++) s += q[d] * Ks[k][d];
            s *= 0.125f;
            float mnew  = fmaxf(m, s);
            float scale = __expf(m - mnew);
            float p     = __expf(s - mnew);
            l = l * scale + p;
#pragma unroll
            for (int d = 0; d < 64; d++) acc[d] = acc[d] * scale + p * Vs[k][d];
            m = mnew;
        }
        __syncthreads();
    }
    float invl = 1.f / l;
    float* o = out + (size_t)t * Dd + h * 64;
#pragma unroll
    for (int d = 0; d < 64; d++) o[d] = acc[d] * invl;
}

// router: logits = g @ router_w (D x 8), sigmoid + top2, build per-expert token lists
__global__ void router_kernel(const float* __restrict__ g, const float* __restrict__ rw,
                              int* __restrict__ cnt, int* __restrict__ idx,
                              float* __restrict__ sc) {
    int t = blockIdx.x;
    int warp = threadIdx.x >> 5, lane = threadIdx.x & 31;
    const float* gr = g + (size_t)t * Dd;
    float acc = 0.f;
    for (int d = lane; d < Dd; d += 32) acc += gr[d] * rw[(size_t)d * Ee + warp];
    for (int o = 16; o; o >>= 1) acc += __shfl_xor_sync(0xffffffffu, acc, o);
    __shared__ float lg[Ee];
    if (lane == 0) lg[warp] = acc;
    __syncthreads();
    if (threadIdx.x == 0) {
        int b1 = 0;
        for (int e = 1; e < Ee; e++) if (lg[e] > lg[b1]) b1 = e;
        int b2 = -1;
        for (int e = 0; e < Ee; e++) {
            if (e == b1) continue;
            if (b2 < 0 || lg[e] > lg[b2]) b2 = e;
        }
        int p1 = atomicAdd(&cnt[b1], 1);
        idx[b1 * Ttok + p1] = t;
        sc [b1 * Ttok + p1] = 1.f / (1.f + expf(-lg[b1]));
        int p2 = atomicAdd(&cnt[b2], 1);
        idx[b2 * Ttok + p2] = t;
        sc [b2 * Ttok + p2] = 1.f / (1.f + expf(-lg[b2]));
    }
}

// silu(gate)*up ; works for shared (cnt==nullptr, e forced 0 by grid size) and experts
__global__ void act_kernel(const float* __restrict__ gu, float* __restrict__ hid,
                           const int* __restrict__ cnt) {
    long gidx = (long)blockIdx.x * 256 + threadIdx.x;
    int e = (int)(gidx / ((long)Ttok * 1024));
    long rem = gidx % ((long)Ttok * 1024);
    int m = (int)(rem >> 10);
    int i = (int)(rem & 1023);
    int Meff = cnt ? cnt[e] : Ttok;
    if (m >= Meff) return;
    const float* gup = gu + (size_t)e * Ttok * 2048 + (size_t)m * 2048;
    float gate = gup[i], up = gup[1024 + i];
    hid[(size_t)e * Ttok * 1024 + (size_t)m * 1024 + i] = gate / (1.f + expf(-gate)) * up;
}

// ---------------- generic SGEMM: 128x128x8 tile, 256 threads, 8x8 per thread ----------------
// GATHER_A: A rows gathered via rowIdx and scaled by rowScale
// CMODE: 0 -> C = A@B ; 1 -> C = A@B + Cadd ; 2 -> C[rowIdx[r]] += A@B  (scatter-accumulate)
template<int GATHER_A, int CMODE>
__global__ __launch_bounds__(256)
void sgemm_kernel(const float* __restrict__ A, const float* __restrict__ Bm,
                  float* __restrict__ C, const float* __restrict__ Cadd,
                  int M, int N, int K, int lda, int ldb, int ldc,
                  const int* __restrict__ rowIdx, const float* __restrict__ rowScale,
                  const int* __restrict__ cntPtr,
                  long eBstride, long eCstride) {
    int e = blockIdx.z;
    int Meff = cntPtr ? cntPtr[e] : M;
    if ((int)blockIdx.y * 128 >= Meff) return;

    const int*   rI = rowIdx   ? rowIdx   + (size_t)e * Ttok : nullptr;
    const float* rS = rowScale ? rowScale + (size_t)e * Ttok : nullptr;
    const float* Bp = Bm + (size_t)e * eBstride;
    float*       Cp = C  + (size_t)e * eCstride;

    __shared__ float As[8][128];
    __shared__ float Bs[8][128];

    int tid = threadIdx.x;
    int tx = tid & 15, ty = tid >> 4;
    int row0 = blockIdx.y * 128, col0 = blockIdx.x * 128;

    int a_r = tid >> 1;           // 0..127
    int a_c = (tid & 1) * 4;      // 0 or 4
    int b_r = tid >> 5;           // 0..7
    int b_c = (tid & 31) * 4;     // 0..124

    float acc[8][8];
#pragma unroll
    for (int i = 0; i < 8; i++)
#pragma unroll
        for (int j = 0; j < 8; j++) acc[i][j] = 0.f;

    int am = row0 + a_r;
    bool avalid = (am < Meff);
    const float* arow = A;
    float ascale = 1.f;
    if (avalid) {
        int src = GATHER_A ? rI[am] : am;
        arow = A + (size_t)src * lda;
        if (GATHER_A) ascale = rS[am];
    }

    for (int k0 = 0; k0 < K; k0 += 8) {
        float4 av = avalid ? *(const float4*)(arow + k0 + a_c) : make_float4(0.f, 0.f, 0.f, 0.f);
        As[a_c + 0][a_r] = av.x * ascale;
        As[a_c + 1][a_r] = av.y * ascale;
        As[a_c + 2][a_r] = av.z * ascale;
        As[a_c + 3][a_r] = av.w * ascale;
        *(float4*)&Bs[b_r][b_c] = *(const float4*)(Bp + (size_t)(k0 + b_r) * ldb + col0 + b_c);
        __syncthreads();
#pragma unroll
        for (int kk = 0; kk < 8; kk++) {
            float ra[8], rb[8];
#pragma unroll
            for (int i = 0; i < 8; i++) ra[i] = As[kk][ty * 8 + i];
#pragma unroll
            for (int j = 0; j < 8; j++) rb[j] = Bs[kk][tx * 8 + j];
#pragma unroll
            for (int i = 0; i < 8; i++)
#pragma unroll
                for (int j = 0; j < 8; j++) acc[i][j] += ra[i] * rb[j];
        }
        __syncthreads();
    }

#pragma unroll
    for (int i = 0; i < 8; i++) {
        int r = row0 + ty * 8 + i;
        if (r >= Meff) continue;
        float* cp;
        if (CMODE == 2) cp = Cp + (size_t)rI[r] * ldc + col0 + tx * 8;
        else            cp = Cp + (size_t)r      * ldc + col0 + tx * 8;
#pragma unroll
        for (int j = 0; j < 8; j++) {
            float v = acc[i][j];
            if (CMODE == 1) v += Cadd[(size_t)r * ldc + col0 + tx * 8 + j];
            if (CMODE == 2) cp[j] += v;
            else            cp[j]  = v;
        }
    }
}

// ---------------- host orchestration ----------------
extern "C" void kernel_launch(void* const* d_in, const int* in_sizes, int n_in,
                              void* d_out, int out_size) {
    const float* x     = (const float*)d_in[0];
    // d_in[1] last_pos (zeros) unused; d_in[3] mask (causal) unused
    const float* rope  = (const float*)d_in[2];
    const float* w_qkv = (const float*)d_in[4];
    const float* w_o   = (const float*)d_in[5];
    const float* n1    = (const float*)d_in[6];
    const float* n2    = (const float*)d_in[7];
    const float* rw    = (const float*)d_in[8];
    const float* wgu   = (const float*)d_in[9];
    const float* wdn   = (const float*)d_in[10];
    const float* sg    = (const float*)d_in[11];
    const float* su    = (const float*)d_in[12];
    const float* sd    = (const float*)d_in[13];
    float* out = (float*)d_out;

    float *h, *qkv, *attn, *h1, *gu, *hid, *sc;
    int *cnt, *idx;
    cudaGetSymbolAddress((void**)&h,    g_h);
    cudaGetSymbolAddress((void**)&qkv,  g_qkv);
    cudaGetSymbolAddress((void**)&attn, g_attn);
    cudaGetSymbolAddress((void**)&h1,   g_h1);
    cudaGetSymbolAddress((void**)&gu,   g_gu);
    cudaGetSymbolAddress((void**)&hid,  g_hid);
    cudaGetSymbolAddress((void**)&cnt,  g_cnt);
    cudaGetSymbolAddress((void**)&idx,  g_idx);
    cudaGetSymbolAddress((void**)&sc,   g_sc);

    zero_cnt_kernel<<<1, 32>>>(cnt);

    // h = rmsnorm(x) * norm1_w
    rmsnorm_kernel<<<Ttok, 256>>>(x, n1, h);

    // qkv = h @ w_qkv   (2048 x 3072 x 2048)
    sgemm_kernel<0, 0><<<dim3(QKVW / 128, Ttok / 128), 256>>>(
        h, w_qkv, qkv, nullptr, Ttok, QKVW, Dd, Dd, QKVW, QKVW,
        nullptr, nullptr, nullptr, 0, 0);

    // rope in-place on q,k
    rope_kernel<<<(Ttok * 40 * 32 + 255) / 256, 256>>>(qkv, rope);

    // attention -> attn (T x 2048)
    attn_kernel<<<dim3(Ss / 64, Hh, Bb), 64>>>(qkv, attn);

    // h1 = x + attn @ w_o
    sgemm_kernel<0, 1><<<dim3(Dd / 128, Ttok / 128), 256>>>(
        attn, w_o, h1, x, Ttok, Dd, Dd, Dd, Dd, Dd,
        nullptr, nullptr, nullptr, 0, 0);

    // g = rmsnorm(h1) * norm2_w  (reuse h)
    rmsnorm_kernel<<<Ttok, 256>>>(h1, n2, h);

    // router: top-2 expert lists
    router_kernel<<<Ttok, 256>>>(h, rw, cnt, idx, sc);

    // shared expert: gu[:, :1024] = g@shared_gate ; gu[:, 1024:] = g@shared_up
    sgemm_kernel<0, 0><<<dim3(Ii / 128, Ttok / 128), 256>>>(
        h, sg, gu, nullptr, Ttok, Ii, Dd, Dd, Ii, 2048,
        nullptr, nullptr, nullptr, 0, 0);
    sgemm_kernel<0, 0><<<dim3(Ii / 128, Ttok / 128), 256>>>(
        h, su, gu + 1024, nullptr, Ttok, Ii, Dd, Dd, Ii, 2048,
        nullptr, nullptr, nullptr, 0, 0);
    act_kernel<<<(Ttok * 1024) / 256, 256>>>(gu, hid, nullptr);

    // out = h1 + hid_shared @ shared_down   (initializes all of d_out)
    sgemm_kernel<0, 1><<<dim3(Dd / 128, Ttok / 128), 256>>>(
        hid, sd, out, h1, Ttok, Dd, Ii, Ii, Dd, Dd,
        nullptr, nullptr, nullptr, 0, 0);

    // routed experts: fused gate_up over all 8 experts (gridDim.z = 8)
    sgemm_kernel<1, 0><<<dim3(2048 / 128, Ttok / 128, Ee), 256>>>(
        h, wgu, gu, nullptr, Ttok, 2048, Dd, Dd, 2048, 2048,
        idx, sc, cnt, (long)Dd * 2048, (long)Ttok * 2048);

    // fused activation over all experts
    act_kernel<<<(Ee * Ttok * 1024) / 256, 256>>>(gu, hid, cnt);

    // down projections: sequential per expert (deterministic scatter-accumulate into out)
    for (int e = 0; e < Ee; e++) {
        sgemm_kernel<0, 2><<<dim3(Dd / 128, Ttok / 128), 256>>>(
            hid + (size_t)e * Ttok * 1024, wdn + (size_t)e * Ii * Dd, out, nullptr,
            Ttok, Dd, Ii, Ii, Dd, Dd,
            idx + e * Ttok, nullptr, cnt + e, 0, 0);
    }
}

// round 3
// speedup vs baseline: 1.2499x; 1.2499x over previous
#include <cuda_runtime.h>
#include <math.h>
#include <stdint.h>

// ---------------- problem constants ----------------
constexpr int Bb   = 2;
constexpr int Ss   = 1024;
constexpr int Dd   = 2048;
constexpr int Hh   = 32;
constexpr int HKV  = 8;
constexpr int HDh  = 64;
constexpr int Ee   = 8;
constexpr int Ii   = 1024;
constexpr int Ttok = Bb * Ss;                 // 2048 tokens
constexpr int QKVW = (Hh + 2 * HKV) * HDh;    // 3072
constexpr int KOFF = Hh * HDh;                // 2048
constexpr int VOFF = (Hh + HKV) * HDh;        // 2560

// ---------------- scratch (device globals; no allocations allowed) ----------------
__device__ float g_h   [(size_t)Ttok * Dd];
__device__ float g_qkv [(size_t)Ttok * QKVW];
__device__ float g_attn[(size_t)Ttok * Dd];
__device__ float g_h1  [(size_t)Ttok * Dd];
__device__ float g_gu  [(size_t)Ee * Ttok * 2048];
__device__ float g_hid [(size_t)Ee * Ttok * 1024];
__device__ int   g_cnt [Ee];
__device__ int   g_idx [Ee * Ttok];
__device__ float g_sc  [Ee * Ttok];

// ---------------- helpers ----------------
__device__ __forceinline__ uint32_t f2tf(float x) {
    uint32_t u;
    asm("cvt.rna.tf32.f32 %0, %1;" : "=r"(u) : "f"(x));
    return u;
}

__device__ __forceinline__ void mma_tf32(float c[4], uint32_t a0, uint32_t a1,
                                         uint32_t a2, uint32_t a3,
                                         uint32_t b0, uint32_t b1) {
    asm volatile(
        "mma.sync.aligned.m16n8k8.row.col.f32.tf32.tf32.f32 "
        "{%0,%1,%2,%3}, {%4,%5,%6,%7}, {%8,%9}, {%0,%1,%2,%3};"
        : "+f"(c[0]), "+f"(c[1]), "+f"(c[2]), "+f"(c[3])
        : "r"(a0), "r"(a1), "r"(a2), "r"(a3), "r"(b0), "r"(b1));
}

// ---------------- small kernels ----------------
__global__ void zero_cnt_kernel(int* cnt) {
    if (threadIdx.x < Ee) cnt[threadIdx.x] = 0;
}

__global__ void rmsnorm_kernel(const float* __restrict__ x, const float* __restrict__ w,
                               float* __restrict__ out) {
    int row = blockIdx.x;
    const float* xr = x + (size_t)row * Dd;
    float ss = 0.f;
    for (int i = threadIdx.x; i < Dd; i += 256) { float v = xr[i]; ss += v * v; }
    __shared__ float red[256];
    red[threadIdx.x] = ss; __syncthreads();
    for (int s = 128; s > 0; s >>= 1) {
        if (threadIdx.x < s) red[threadIdx.x] += red[threadIdx.x + s];
        __syncthreads();
    }
    float inv = rsqrtf(red[0] / (float)Dd + 1e-5f);
    float* orow = out + (size_t)row * Dd;
    for (int i = threadIdx.x; i < Dd; i += 256) orow[i] = xr[i] * inv * w[i];
}

__global__ void rope_kernel(float* __restrict__ qkv, const float* __restrict__ cache) {
    int idx = blockIdx.x * blockDim.x + threadIdx.x;
    const int TOT = Ttok * 40 * 32;
    if (idx >= TOT) return;
    int p  = idx & 31;
    int hh = (idx >> 5) % 40;
    int t  = idx / (32 * 40);
    int s  = t % Ss;
    float c  = cache[((size_t)s * 32 + p) * 2 + 0];
    float sn = cache[((size_t)s * 32 + p) * 2 + 1];
    float* base = qkv + (size_t)t * QKVW + hh * 64 + 2 * p;
    float x0 = base[0], x1 = base[1];
    base[0] = x0 * c - x1 * sn;
    base[1] = x1 * c + x0 * sn;
}

// flash attention: grid (S/64, H, B), 64 threads; thread = one query row
__global__ __launch_bounds__(64)
void attn_kernel(const float* __restrict__ qkv, float* __restrict__ out) {
    int qt = blockIdx.x, h = blockIdx.y, b = blockIdx.z;
    int tid = threadIdx.x;
    int qi = qt * 64 + tid;
    int t  = b * Ss + qi;
    int kvh = h >> 2;

    const float* qrow = qkv + (size_t)t * QKVW + h * 64;
    float q[64], acc[64];
#pragma unroll
    for (int d = 0; d < 64; d++) { q[d] = qrow[d]; acc[d] = 0.f; }
    float m = -1e30f, l = 0.f;

    __shared__ float Ks[64][64];
    __shared__ float Vs[64][64];

    int ktiles = qt + 1;
    for (int kt = 0; kt < ktiles; kt++) {
        const float* krow = qkv + (size_t)(b * Ss + kt * 64 + tid) * QKVW + KOFF + kvh * 64;
        const float* vrow = qkv + (size_t)(b * Ss + kt * 64 + tid) * QKVW + VOFF + kvh * 64;
#pragma unroll 8
        for (int d = 0; d < 64; d++) { Ks[tid][d] = krow[d]; Vs[tid][d] = vrow[d]; }
        __syncthreads();
        int kmax = qi - kt * 64 + 1;
        if (kmax > 64) kmax = 64;
        for (int k = 0; k < kmax; k++) {
            float s0 = 0.f, s1 = 0.f, s2 = 0.f, s3 = 0.f;
#pragma unroll
            for (int d = 0; d < 64; d += 4) {
                s0 += q[d + 0] * Ks[k][d + 0];
                s1 += q[d + 1] * Ks[k][d + 1];
                s2 += q[d + 2] * Ks[k][d + 2];
                s3 += q[d + 3] * Ks[k][d + 3];
            }
            float s = ((s0 + s1) + (s2 + s3)) * 0.125f;
            if (s > m) {
                float scale = __expf(m - s);
                l *= scale;
#pragma unroll
                for (int d = 0; d < 64; d++) acc[d] *= scale;
                m = s;
            }
            float p = __expf(s - m);
            l += p;
#pragma unroll
            for (int d = 0; d < 64; d++) acc[d] += p * Vs[k][d];
        }
        __syncthreads();
    }
    float invl = 1.f / l;
    float* o = out + (size_t)t * Dd + h * 64;
#pragma unroll
    for (int d = 0; d < 64; d++) o[d] = acc[d] * invl;
}

__global__ void router_kernel(const float* __restrict__ g, const float* __restrict__ rw,
                              int* __restrict__ cnt, int* __restrict__ idx,
                              float* __restrict__ sc) {
    int t = blockIdx.x;
    int warp = threadIdx.x >> 5, lane = threadIdx.x & 31;
    const float* gr = g + (size_t)t * Dd;
    float acc = 0.f;
    for (int d = lane; d < Dd; d += 32) acc += gr[d] * rw[(size_t)d * Ee + warp];
    for (int o = 16; o; o >>= 1) acc += __shfl_xor_sync(0xffffffffu, acc, o);
    __shared__ float lg[Ee];
    if (lane == 0) lg[warp] = acc;
    __syncthreads();
    if (threadIdx.x == 0) {
        int b1 = 0;
        for (int e = 1; e < Ee; e++) if (lg[e] > lg[b1]) b1 = e;
        int b2 = -1;
        for (int e = 0; e < Ee; e++) {
            if (e == b1) continue;
            if (b2 < 0 || lg[e] > lg[b2]) b2 = e;
        }
        int p1 = atomicAdd(&cnt[b1], 1);
        idx[b1 * Ttok + p1] = t;
        sc [b1 * Ttok + p1] = 1.f / (1.f + expf(-lg[b1]));
        int p2 = atomicAdd(&cnt[b2], 1);
        idx[b2 * Ttok + p2] = t;
        sc [b2 * Ttok + p2] = 1.f / (1.f + expf(-lg[b2]));
    }
}

__global__ void act_kernel(const float* __restrict__ gu, float* __restrict__ hid,
                           const int* __restrict__ cnt) {
    long gidx = (long)blockIdx.x * 256 + threadIdx.x;
    int e = (int)(gidx / ((long)Ttok * 1024));
    long rem = gidx % ((long)Ttok * 1024);
    int m = (int)(rem >> 10);
    int i = (int)(rem & 1023);
    int Meff = cnt ? cnt[e] : Ttok;
    if (m >= Meff) return;
    const float* gup = gu + (size_t)e * Ttok * 2048 + (size_t)m * 2048;
    float gate = gup[i], up = gup[1024 + i];
    hid[(size_t)e * Ttok * 1024 + (size_t)m * 1024 + i] = gate / (1.f + expf(-gate)) * up;
}

// ---------------- 3xTF32 tensor-core GEMM (fp32-accurate) ----------------
// CTA tile 128x128, BK=16; 8 warps (2m x 4n), warp tile 64x32 -> 4x4 m16n8k8 MMAs
// Each operand split hi/lo: C += aH*bH + aH*bL + aL*bH  (error ~2^-22)
// CMODE: 0 C=AB ; 1 C=AB+Cadd ; 2 C[rowIdx[r]] += AB (scatter-accumulate)
template<int GATHER_A, int CMODE>
__global__ __launch_bounds__(256)
void tgemm_kernel(const float* __restrict__ A, const float* __restrict__ Bm,
                  float* __restrict__ C, const float* __restrict__ Cadd,
                  int M, int N, int K, int lda, int ldb, int ldc,
                  const int* __restrict__ rowIdx, const float* __restrict__ rowScale,
                  const int* __restrict__ cntPtr,
                  long eBstride, long eCstride) {
    int e = blockIdx.z;
    int Meff = cntPtr ? cntPtr[e] : M;
    int row0 = blockIdx.y * 128, col0 = blockIdx.x * 128;
    if (row0 >= Meff) return;

    const int*   rI = rowIdx   ? rowIdx   + (size_t)e * Ttok : nullptr;
    const float* rS = rowScale ? rowScale + (size_t)e * Ttok : nullptr;
    const float* Bp = Bm + (size_t)e * eBstride;
    float*       Cp = C  + (size_t)e * eCstride;

    // k-major smem, stride 136 (bank = 8k+idx -> conflict-free frags)
    __shared__ uint32_t AsH[16][136];
    __shared__ uint32_t AsL[16][136];
    __shared__ uint32_t BsH[16][136];
    __shared__ uint32_t BsL[16][136];

    int tid  = threadIdx.x;
    int lane = tid & 31;
    int wid  = tid >> 5;
    int warp_m = (wid & 1) * 64;
    int warp_n = (wid >> 1) * 32;
    int lr = lane >> 2, lc = lane & 3;

    // A loader: thread owns row (tid&127), 8 consecutive k
    int a_row = tid & 127;
    int a_k0  = (tid >> 7) * 8;
    int gm = row0 + a_row;
    bool avalid = (gm < Meff);
    const float* arow = A;
    float ascale = 1.f;
    if (avalid) {
        int src = GATHER_A ? rI[gm] : gm;
        arow = A + (size_t)src * lda;
        if (GATHER_A) ascale = rS[gm];
    }
    // B loader: thread owns k-row (tid>>4), 8 consecutive n
    int b_k  = tid >> 4;
    int b_n0 = (tid & 15) * 8;

    float c[4][4][4];
#pragma unroll
    for (int mi = 0; mi < 4; mi++)
#pragma unroll
        for (int ni = 0; ni < 4; ni++)
#pragma unroll
            for (int r = 0; r < 4; r++) c[mi][ni][r] = 0.f;

    float aR[8], bR[8];

    auto loadStage = [&](int k0) {
        if (avalid) {
            float4 v0 = *(const float4*)(arow + k0 + a_k0);
            float4 v1 = *(const float4*)(arow + k0 + a_k0 + 4);
            aR[0] = v0.x * ascale; aR[1] = v0.y * ascale;
            aR[2] = v0.z * ascale; aR[3] = v0.w * ascale;
            aR[4] = v1.x * ascale; aR[5] = v1.y * ascale;
            aR[6] = v1.z * ascale; aR[7] = v1.w * ascale;
        } else {
#pragma unroll
            for (int i = 0; i < 8; i++) aR[i] = 0.f;
        }
        const float* brow = Bp + (size_t)(k0 + b_k) * ldb + col0 + b_n0;
        float4 w0 = *(const float4*)(brow);
        float4 w1 = *(const float4*)(brow + 4);
        bR[0] = w0.x; bR[1] = w0.y; bR[2] = w0.z; bR[3] = w0.w;
        bR[4] = w1.x; bR[5] = w1.y; bR[6] = w1.z; bR[7] = w1.w;
    };

    auto storeStage = [&]() {
#pragma unroll
        for (int i = 0; i < 8; i++) {
            uint32_t hi = f2tf(aR[i]);
            uint32_t lo = f2tf(aR[i] - __uint_as_float(hi));
            AsH[a_k0 + i][a_row] = hi;
            AsL[a_k0 + i][a_row] = lo;
        }
        uint4 h4, l4;
        h4.x = f2tf(bR[0]); h4.y = f2tf(bR[1]); h4.z = f2tf(bR[2]); h4.w = f2tf(bR[3]);
        l4.x = f2tf(bR[0] - __uint_as_float(h4.x));
        l4.y = f2tf(bR[1] - __uint_as_float(h4.y));
        l4.z = f2tf(bR[2] - __uint_as_float(h4.z));
        l4.w = f2tf(bR[3] - __uint_as_float(h4.w));
        *(uint4*)&BsH[b_k][b_n0] = h4;
        *(uint4*)&BsL[b_k][b_n0] = l4;
        h4.x = f2tf(bR[4]); h4.y = f2tf(bR[5]); h4.z = f2tf(bR[6]); h4.w = f2tf(bR[7]);
        l4.x = f2tf(bR[4] - __uint_as_float(h4.x));
        l4.y = f2tf(bR[5] - __uint_as_float(h4.y));
        l4.z = f2tf(bR[6] - __uint_as_float(h4.z));
        l4.w = f2tf(bR[7] - __uint_as_float(h4.w));
        *(uint4*)&BsH[b_k][b_n0 + 4] = h4;
        *(uint4*)&BsL[b_k][b_n0 + 4] = l4;
    };

    int nk = K >> 4;
    loadStage(0);
    storeStage();

    for (int kt = 0; kt < nk; kt++) {
        __syncthreads();
        bool more = (kt + 1) < nk;
        if (more) loadStage((kt + 1) << 4);   // LDGs overlap with MMAs below

#pragma unroll
        for (int ks = 0; ks < 2; ks++) {
            int kb = ks * 8;
            uint32_t aH[4][4], aL[4][4];
#pragma unroll
            for (int mi = 0; mi < 4; mi++) {
                int r = warp_m + mi * 16 + lr;
                aH[mi][0] = AsH[kb + lc    ][r];
                aH[mi][1] = AsH[kb + lc    ][r + 8];
                aH[mi][2] = AsH[kb + lc + 4][r];
                aH[mi][3] = AsH[kb + lc + 4][r + 8];
                aL[mi][0] = AsL[kb + lc    ][r];
                aL[mi][1] = AsL[kb + lc    ][r + 8];
                aL[mi][2] = AsL[kb + lc + 4][r];
                aL[mi][3] = AsL[kb + lc + 4][r + 8];
            }
            uint32_t bH[4][2], bL[4][2];
#pragma unroll
            for (int ni = 0; ni < 4; ni++) {
                int cn = warp_n + ni * 8 + lr;
                bH[ni][0] = BsH[kb + lc    ][cn];
                bH[ni][1] = BsH[kb + lc + 4][cn];
                bL[ni][0] = BsL[kb + lc    ][cn];
                bL[ni][1] = BsL[kb + lc + 4][cn];
            }
#pragma unroll
            for (int mi = 0; mi < 4; mi++)
#pragma unroll
                for (int ni = 0; ni < 4; ni++) {
                    mma_tf32(c[mi][ni], aL[mi][0], aL[mi][1], aL[mi][2], aL[mi][3],
                             bH[ni][0], bH[ni][1]);
                    mma_tf32(c[mi][ni], aH[mi][0], aH[mi][1], aH[mi][2], aH[mi][3],
                             bL[ni][0], bL[ni][1]);
                    mma_tf32(c[mi][ni], aH[mi][0], aH[mi][1], aH[mi][2], aH[mi][3],
                             bH[ni][0], bH[ni][1]);
                }
        }
        __syncthreads();
        if (more) storeStage();
    }

    // epilogue
#pragma unroll
    for (int mi = 0; mi < 4; mi++) {
        int r0 = row0 + warp_m + mi * 16 + lr;
        int r1 = r0 + 8;
#pragma unroll
        for (int ni = 0; ni < 4; ni++) {
            int cc = col0 + warp_n + ni * 8 + 2 * lc;
            if (r0 < Meff) {
                float v0 = c[mi][ni][0], v1 = c[mi][ni][1];
                if (CMODE == 1) {
                    v0 += Cadd[(size_t)r0 * ldc + cc];
                    v1 += Cadd[(size_t)r0 * ldc + cc + 1];
                }
                if (CMODE == 2) {
                    float* cp = Cp + (size_t)rI[r0] * ldc + cc;
                    cp[0] += v0; cp[1] += v1;
                } else {
                    float* cp = Cp + (size_t)r0 * ldc + cc;
                    cp[0] = v0; cp[1] = v1;
                }
            }
            if (r1 < Meff) {
                float v2 = c[mi][ni][2], v3 = c[mi][ni][3];
                if (CMODE == 1) {
                    v2 += Cadd[(size_t)r1 * ldc + cc];
                    v3 += Cadd[(size_t)r1 * ldc + cc + 1];
                }
                if (CMODE == 2) {
                    float* cp = Cp + (size_t)rI[r1] * ldc + cc;
                    cp[0] += v2; cp[1] += v3;
                } else {
                    float* cp = Cp + (size_t)r1 * ldc + cc;
                    cp[0] = v2; cp[1] = v3;
                }
            }
        }
    }
}

// ---------------- host orchestration ----------------
extern "C" void kernel_launch(void* const* d_in, const int* in_sizes, int n_in,
                              void* d_out, int out_size) {
    const float* x     = (const float*)d_in[0];
    const float* rope  = (const float*)d_in[2];
    const float* w_qkv = (const float*)d_in[4];
    const float* w_o   = (const float*)d_in[5];
    const float* n1    = (const float*)d_in[6];
    const float* n2    = (const float*)d_in[7];
    const float* rw    = (const float*)d_in[8];
    const float* wgu   = (const float*)d_in[9];
    const float* wdn   = (const float*)d_in[10];
    const float* sg    = (const float*)d_in[11];
    const float* su    = (const float*)d_in[12];
    const float* sd    = (const float*)d_in[13];
    float* out = (float*)d_out;

    float *h, *qkv, *attn, *h1, *gu, *hid, *sc;
    int *cnt, *idx;
    cudaGetSymbolAddress((void**)&h,    g_h);
    cudaGetSymbolAddress((void**)&qkv,  g_qkv);
    cudaGetSymbolAddress((void**)&attn, g_attn);
    cudaGetSymbolAddress((void**)&h1,   g_h1);
    cudaGetSymbolAddress((void**)&gu,   g_gu);
    cudaGetSymbolAddress((void**)&hid,  g_hid);
    cudaGetSymbolAddress((void**)&cnt,  g_cnt);
    cudaGetSymbolAddress((void**)&idx,  g_idx);
    cudaGetSymbolAddress((void**)&sc,   g_sc);

    zero_cnt_kernel<<<1, 32>>>(cnt);

    rmsnorm_kernel<<<Ttok, 256>>>(x, n1, h);

    // qkv = h @ w_qkv
    tgemm_kernel<0, 0><<<dim3(QKVW / 128, Ttok / 128), 256>>>(
        h, w_qkv, qkv, nullptr, Ttok, QKVW, Dd, Dd, QKVW, QKVW,
        nullptr, nullptr, nullptr, 0, 0);

    rope_kernel<<<(Ttok * 40 * 32 + 255) / 256, 256>>>(qkv, rope);

    attn_kernel<<<dim3(Ss / 64, Hh, Bb), 64>>>(qkv, attn);

    // h1 = x + attn @ w_o
    tgemm_kernel<0, 1><<<dim3(Dd / 128, Ttok / 128), 256>>>(
        attn, w_o, h1, x, Ttok, Dd, Dd, Dd, Dd, Dd,
        nullptr, nullptr, nullptr, 0, 0);

    rmsnorm_kernel<<<Ttok, 256>>>(h1, n2, h);

    router_kernel<<<Ttok, 256>>>(h, rw, cnt, idx, sc);

    // shared expert gate & up
    tgemm_kernel<0, 0><<<dim3(Ii / 128, Ttok / 128), 256>>>(
        h, sg, gu, nullptr, Ttok, Ii, Dd, Dd, Ii, 2048,
        nullptr, nullptr, nullptr, 0, 0);
    tgemm_kernel<0, 0><<<dim3(Ii / 128, Ttok / 128), 256>>>(
        h, su, gu + 1024, nullptr, Ttok, Ii, Dd, Dd, Ii, 2048,
        nullptr, nullptr, nullptr, 0, 0);
    act_kernel<<<(Ttok * 1024) / 256, 256>>>(gu, hid, nullptr);

    // out = h1 + hid_shared @ shared_down
    tgemm_kernel<0, 1><<<dim3(Dd / 128, Ttok / 128), 256>>>(
        hid, sd, out, h1, Ttok, Dd, Ii, Ii, Dd, Dd,
        nullptr, nullptr, nullptr, 0, 0);

    // routed experts gate_up (gathered rows, scaled), all 8 experts in z
    tgemm_kernel<1, 0><<<dim3(2048 / 128, Ttok / 128, Ee), 256>>>(
        h, wgu, gu, nullptr, Ttok, 2048, Dd, Dd, 2048, 2048,
        idx, sc, cnt, (long)Dd * 2048, (long)Ttok * 2048);

    act_kernel<<<(Ee * Ttok * 1024) / 256, 256>>>(gu, hid, cnt);

    // routed down projections: sequential scatter-accumulate (deterministic)
    for (int e = 0; e < Ee; e++) {
        tgemm_kernel<0, 2><<<dim3(Dd / 128, Ttok / 128), 256>>>(
            hid + (size_t)e * Ttok * 1024, wdn + (size_t)e * Ii * Dd, out, nullptr,
            Ttok, Dd, Ii, Ii, Dd, Dd,
            idx + e * Ttok, nullptr, cnt + e, 0, 0);
    }
}

// round 4
// speedup vs baseline: 1.8367x; 1.4695x over previous
#include <cuda_runtime.h>
#include <math.h>
#include <stdint.h>

// ---------------- problem constants ----------------
constexpr int Bb   = 2;
constexpr int Ss   = 1024;
constexpr int Dd   = 2048;
constexpr int Hh   = 32;
constexpr int HKV  = 8;
constexpr int HDh  = 64;
constexpr int Ee   = 8;
constexpr int Ii   = 1024;
constexpr int Ttok = Bb * Ss;                 // 2048 tokens
constexpr int QKVW = (Hh + 2 * HKV) * HDh;    // 3072
constexpr int KOFF = Hh * HDh;                // 2048
constexpr int VOFF = (Hh + HKV) * HDh;        // 2560

// ---------------- scratch (device globals; no allocations allowed) ----------------
__device__ float g_h   [(size_t)Ttok * Dd];
__device__ float g_qkv [(size_t)Ttok * QKVW];
__device__ float g_attn[(size_t)Ttok * Dd];    // attn out, later reused as shared-down out
__device__ float g_h1  [(size_t)Ttok * Dd];
__device__ float g_gu  [(size_t)Ee * Ttok * 2048];
__device__ float g_hid [(size_t)Ee * Ttok * 1024];
__device__ float g_eo  [(size_t)Ee * Ttok * Dd];   // per-slot expert down outputs
__device__ int   g_cnt [Ee];
__device__ int   g_idx [Ee * Ttok];
__device__ float g_sc  [Ee * Ttok];
__device__ int   g_slot[Ttok * 2];             // token -> 2 global slot rows (e*Ttok+pos)

// ---------------- helpers ----------------
__device__ __forceinline__ uint32_t f2tf(float x) {
    uint32_t u;
    asm("cvt.rna.tf32.f32 %0, %1;" : "=r"(u) : "f"(x));
    return u;
}

__device__ __forceinline__ void mma_tf32(float c[4], uint32_t a0, uint32_t a1,
                                         uint32_t a2, uint32_t a3,
                                         uint32_t b0, uint32_t b1) {
    asm volatile(
        "mma.sync.aligned.m16n8k8.row.col.f32.tf32.tf32.f32 "
        "{%0,%1,%2,%3}, {%4,%5,%6,%7}, {%8,%9}, {%0,%1,%2,%3};"
        : "+f"(c[0]), "+f"(c[1]), "+f"(c[2]), "+f"(c[3])
        : "r"(a0), "r"(a1), "r"(a2), "r"(a3), "r"(b0), "r"(b1));
}

// ---------------- small kernels ----------------
__global__ void zero_cnt_kernel(int* cnt) {
    if (threadIdx.x < Ee) cnt[threadIdx.x] = 0;
}

__global__ void rmsnorm_kernel(const float* __restrict__ x, const float* __restrict__ w,
                               float* __restrict__ out) {
    int row = blockIdx.x;
    const float* xr = x + (size_t)row * Dd;
    float ss = 0.f;
    for (int i = threadIdx.x; i < Dd; i += 256) { float v = xr[i]; ss += v * v; }
    __shared__ float red[256];
    red[threadIdx.x] = ss; __syncthreads();
    for (int s = 128; s > 0; s >>= 1) {
        if (threadIdx.x < s) red[threadIdx.x] += red[threadIdx.x + s];
        __syncthreads();
    }
    float inv = rsqrtf(red[0] / (float)Dd + 1e-5f);
    float* orow = out + (size_t)row * Dd;
    for (int i = threadIdx.x; i < Dd; i += 256) orow[i] = xr[i] * inv * w[i];
}

__global__ void rope_kernel(float* __restrict__ qkv, const float* __restrict__ cache) {
    int idx = blockIdx.x * blockDim.x + threadIdx.x;
    const int TOT = Ttok * 40 * 32;
    if (idx >= TOT) return;
    int p  = idx & 31;
    int hh = (idx >> 5) % 40;
    int t  = idx / (32 * 40);
    int s  = t % Ss;
    float c  = cache[((size_t)s * 32 + p) * 2 + 0];
    float sn = cache[((size_t)s * 32 + p) * 2 + 1];
    float* base = qkv + (size_t)t * QKVW + hh * 64 + 2 * p;
    float x0 = base[0], x1 = base[1];
    base[0] = x0 * c - x1 * sn;
    base[1] = x1 * c + x0 * sn;
}

// flash attention: grid (S/64, H, B), 64 threads; thread = one query row
__global__ __launch_bounds__(64)
void attn_kernel(const float* __restrict__ qkv, float* __restrict__ out) {
    int qt = blockIdx.x, h = blockIdx.y, b = blockIdx.z;
    int tid = threadIdx.x;
    int qi = qt * 64 + tid;
    int t  = b * Ss + qi;
    int kvh = h >> 2;

    const float* qrow = qkv + (size_t)t * QKVW + h * 64;
    float q[64], acc[64];
#pragma unroll
    for (int d = 0; d < 64; d++) { q[d] = qrow[d]; acc[d] = 0.f; }
    float m = -1e30f, l = 0.f;

    __shared__ float Ks[64][64];
    __shared__ float Vs[64][64];

    int ktiles = qt + 1;
    for (int kt = 0; kt < ktiles; kt++) {
        const float* krow = qkv + (size_t)(b * Ss + kt * 64 + tid) * QKVW + KOFF + kvh * 64;
        const float* vrow = qkv + (size_t)(b * Ss + kt * 64 + tid) * QKVW + VOFF + kvh * 64;
#pragma unroll 8
        for (int d = 0; d < 64; d++) { Ks[tid][d] = krow[d]; Vs[tid][d] = vrow[d]; }
        __syncthreads();
        int kmax = qi - kt * 64 + 1;
        if (kmax > 64) kmax = 64;
        for (int k = 0; k < kmax; k++) {
            float s0 = 0.f, s1 = 0.f, s2 = 0.f, s3 = 0.f;
#pragma unroll
            for (int d = 0; d < 64; d += 4) {
                s0 += q[d + 0] * Ks[k][d + 0];
                s1 += q[d + 1] * Ks[k][d + 1];
                s2 += q[d + 2] * Ks[k][d + 2];
                s3 += q[d + 3] * Ks[k][d + 3];
            }
            float s = ((s0 + s1) + (s2 + s3)) * 0.125f;
            if (s > m) {
                float scale = __expf(m - s);
                l *= scale;
#pragma unroll
                for (int d = 0; d < 64; d++) acc[d] *= scale;
                m = s;
            }
            float p = __expf(s - m);
            l += p;
#pragma unroll
            for (int d = 0; d < 64; d++) acc[d] += p * Vs[k][d];
        }
        __syncthreads();
    }
    float invl = 1.f / l;
    float* o = out + (size_t)t * Dd + h * 64;
#pragma unroll
    for (int d = 0; d < 64; d++) o[d] = acc[d] * invl;
}

__global__ void router_kernel(const float* __restrict__ g, const float* __restrict__ rw,
                              int* __restrict__ cnt, int* __restrict__ idx,
                              float* __restrict__ sc, int* __restrict__ slot) {
    int t = blockIdx.x;
    int warp = threadIdx.x >> 5, lane = threadIdx.x & 31;
    const float* gr = g + (size_t)t * Dd;
    float acc = 0.f;
    for (int d = lane; d < Dd; d += 32) acc += gr[d] * rw[(size_t)d * Ee + warp];
    for (int o = 16; o; o >>= 1) acc += __shfl_xor_sync(0xffffffffu, acc, o);
    __shared__ float lg[Ee];
    if (lane == 0) lg[warp] = acc;
    __syncthreads();
    if (threadIdx.x == 0) {
        int b1 = 0;
        for (int e = 1; e < Ee; e++) if (lg[e] > lg[b1]) b1 = e;
        int b2 = -1;
        for (int e = 0; e < Ee; e++) {
            if (e == b1) continue;
            if (b2 < 0 || lg[e] > lg[b2]) b2 = e;
        }
        int p1 = atomicAdd(&cnt[b1], 1);
        idx[b1 * Ttok + p1] = t;
        sc [b1 * Ttok + p1] = 1.f / (1.f + expf(-lg[b1]));
        slot[t * 2 + 0] = b1 * Ttok + p1;
        int p2 = atomicAdd(&cnt[b2], 1);
        idx[b2 * Ttok + p2] = t;
        sc [b2 * Ttok + p2] = 1.f / (1.f + expf(-lg[b2]));
        slot[t * 2 + 1] = b2 * Ttok + p2;
    }
}

__global__ void act_kernel(const float* __restrict__ gu, float* __restrict__ hid,
                           const int* __restrict__ cnt) {
    long gidx = (long)blockIdx.x * 256 + threadIdx.x;
    int e = (int)(gidx / ((long)Ttok * 1024));
    long rem = gidx % ((long)Ttok * 1024);
    int m = (int)(rem >> 10);
    int i = (int)(rem & 1023);
    int Meff = cnt ? cnt[e] : Ttok;
    if (m >= Meff) return;
    const float* gup = gu + (size_t)e * Ttok * 2048 + (size_t)m * 2048;
    float gate = gup[i], up = gup[1024 + i];
    hid[(size_t)e * Ttok * 1024 + (size_t)m * 1024 + i] = gate / (1.f + expf(-gate)) * up;
}

// out = h1 + shd + eo[slot0] + eo[slot1], vectorized float4
__global__ void add4_kernel(float* __restrict__ out, const float* __restrict__ h1,
                            const float* __restrict__ shd, const float* __restrict__ eo,
                            const int* __restrict__ slot) {
    int gid = blockIdx.x * 256 + threadIdx.x;         // over Ttok * Dd / 4
    int t = gid / (Dd / 4);
    int d4 = gid % (Dd / 4);
    size_t off = (size_t)t * Dd + d4 * 4;
    int s0 = slot[t * 2 + 0], s1 = slot[t * 2 + 1];
    float4 a = *(const float4*)(h1 + off);
    float4 b = *(const float4*)(shd + off);
    float4 c0 = *(const float4*)(eo + (size_t)s0 * Dd + d4 * 4);
    float4 c1 = *(const float4*)(eo + (size_t)s1 * Dd + d4 * 4);
    float4 r;
    r.x = a.x + b.x + c0.x + c1.x;
    r.y = a.y + b.y + c0.y + c1.y;
    r.z = a.z + b.z + c0.z + c1.z;
    r.w = a.w + b.w + c0.w + c1.w;
    *(float4*)(out + off) = r;
}

// ---------------- tf32 tensor-core GEMM, PREC=3 (3xTF32, fp32-accurate) or PREC=1 ----
// CTA tile 128x128, BK=16; 8 warps (2m x 4n), warp tile 64x32 -> 4x4 m16n8k8 MMAs
// CMODE: 0 C=AB ; 1 C=AB+Cadd
template<int GATHER_A, int CMODE, int PREC>
__global__ __launch_bounds__(256)
void tgemm_kernel(const float* __restrict__ A, const float* __restrict__ Bm,
                  float* __restrict__ C, const float* __restrict__ Cadd,
                  int M, int N, int K, int lda, int ldb, int ldc,
                  const int* __restrict__ rowIdx, const float* __restrict__ rowScale,
                  const int* __restrict__ cntPtr,
                  long eAstride, long eBstride, long eCstride) {
    int e = blockIdx.z;
    int Meff = cntPtr ? cntPtr[e] : M;
    int row0 = blockIdx.y * 128, col0 = blockIdx.x * 128;
    if (row0 >= Meff) return;

    const int*   rI = rowIdx   ? rowIdx   + (size_t)e * Ttok : nullptr;
    const float* rS = rowScale ? rowScale + (size_t)e * Ttok : nullptr;
    const float* Ap = A  + (size_t)e * eAstride;
    const float* Bp = Bm + (size_t)e * eBstride;
    float*       Cp = C  + (size_t)e * eCstride;

    constexpr int LO = (PREC == 3);
    __shared__ uint32_t AsH[16][136];
    __shared__ uint32_t BsH[16][136];
    __shared__ uint32_t AsL[LO ? 16 : 1][LO ? 136 : 1];
    __shared__ uint32_t BsL[LO ? 16 : 1][LO ? 136 : 1];

    int tid  = threadIdx.x;
    int lane = tid & 31;
    int wid  = tid >> 5;
    int warp_m = (wid & 1) * 64;
    int warp_n = (wid >> 1) * 32;
    int lr = lane >> 2, lc = lane & 3;

    int a_row = tid & 127;
    int a_k0  = (tid >> 7) * 8;
    int gm = row0 + a_row;
    bool avalid = (gm < Meff);
    const float* arow = Ap;
    float ascale = 1.f;
    if (avalid) {
        int src = GATHER_A ? rI[gm] : gm;
        arow = Ap + (size_t)src * lda;
        if (GATHER_A) ascale = rS[gm];
    }
    int b_k  = tid >> 4;
    int b_n0 = (tid & 15) * 8;

    float c[4][4][4];
#pragma unroll
    for (int mi = 0; mi < 4; mi++)
#pragma unroll
        for (int ni = 0; ni < 4; ni++)
#pragma unroll
            for (int r = 0; r < 4; r++) c[mi][ni][r] = 0.f;

    float aR[8], bR[8];

    auto loadStage = [&](int k0) {
        if (avalid) {
            float4 v0 = *(const float4*)(arow + k0 + a_k0);
            float4 v1 = *(const float4*)(arow + k0 + a_k0 + 4);
            aR[0] = v0.x * ascale; aR[1] = v0.y * ascale;
            aR[2] = v0.z * ascale; aR[3] = v0.w * ascale;
            aR[4] = v1.x * ascale; aR[5] = v1.y * ascale;
            aR[6] = v1.z * ascale; aR[7] = v1.w * ascale;
        } else {
#pragma unroll
            for (int i = 0; i < 8; i++) aR[i] = 0.f;
        }
        const float* brow = Bp + (size_t)(k0 + b_k) * ldb + col0 + b_n0;
        float4 w0 = *(const float4*)(brow);
        float4 w1 = *(const float4*)(brow + 4);
        bR[0] = w0.x; bR[1] = w0.y; bR[2] = w0.z; bR[3] = w0.w;
        bR[4] = w1.x; bR[5] = w1.y; bR[6] = w1.z; bR[7] = w1.w;
    };

    auto storeStage = [&]() {
#pragma unroll
        for (int i = 0; i < 8; i++) {
            uint32_t hi = f2tf(aR[i]);
            AsH[a_k0 + i][a_row] = hi;
            if (LO) AsL[a_k0 + i][a_row] = f2tf(aR[i] - __uint_as_float(hi));
        }
#pragma unroll
        for (int half = 0; half < 2; half++) {
            uint4 h4;
            h4.x = f2tf(bR[half * 4 + 0]); h4.y = f2tf(bR[half * 4 + 1]);
            h4.z = f2tf(bR[half * 4 + 2]); h4.w = f2tf(bR[half * 4 + 3]);
            *(uint4*)&BsH[b_k][b_n0 + half * 4] = h4;
            if (LO) {
                uint4 l4;
                l4.x = f2tf(bR[half * 4 + 0] - __uint_as_float(h4.x));
                l4.y = f2tf(bR[half * 4 + 1] - __uint_as_float(h4.y));
                l4.z = f2tf(bR[half * 4 + 2] - __uint_as_float(h4.z));
                l4.w = f2tf(bR[half * 4 + 3] - __uint_as_float(h4.w));
                *(uint4*)&BsL[b_k][b_n0 + half * 4] = l4;
            }
        }
    };

    int nk = K >> 4;
    loadStage(0);
    storeStage();

    for (int kt = 0; kt < nk; kt++) {
        __syncthreads();
        bool more = (kt + 1) < nk;
        if (more) loadStage((kt + 1) << 4);

#pragma unroll
        for (int ks = 0; ks < 2; ks++) {
            int kb = ks * 8;
            uint32_t aH[4][4], aL[4][4];
#pragma unroll
            for (int mi = 0; mi < 4; mi++) {
                int r = warp_m + mi * 16 + lr;
                aH[mi][0] = AsH[kb + lc    ][r];
                aH[mi][1] = AsH[kb + lc    ][r + 8];
                aH[mi][2] = AsH[kb + lc + 4][r];
                aH[mi][3] = AsH[kb + lc + 4][r + 8];
                if (LO) {
                    aL[mi][0] = AsL[kb + lc    ][r];
                    aL[mi][1] = AsL[kb + lc    ][r + 8];
                    aL[mi][2] = AsL[kb + lc + 4][r];
                    aL[mi][3] = AsL[kb + lc + 4][r + 8];
                }
            }
            uint32_t bH[4][2], bL[4][2];
#pragma unroll
            for (int ni = 0; ni < 4; ni++) {
                int cn = warp_n + ni * 8 + lr;
                bH[ni][0] = BsH[kb + lc    ][cn];
                bH[ni][1] = BsH[kb + lc + 4][cn];
                if (LO) {
                    bL[ni][0] = BsL[kb + lc    ][cn];
                    bL[ni][1] = BsL[kb + lc + 4][cn];
                }
            }
#pragma unroll
            for (int mi = 0; mi < 4; mi++)
#pragma unroll
                for (int ni = 0; ni < 4; ni++) {
                    if (LO) {
                        mma_tf32(c[mi][ni], aL[mi][0], aL[mi][1], aL[mi][2], aL[mi][3],
                                 bH[ni][0], bH[ni][1]);
                        mma_tf32(c[mi][ni], aH[mi][0], aH[mi][1], aH[mi][2], aH[mi][3],
                                 bL[ni][0], bL[ni][1]);
                    }
                    mma_tf32(c[mi][ni], aH[mi][0], aH[mi][1], aH[mi][2], aH[mi][3],
                             bH[ni][0], bH[ni][1]);
                }
        }
        __syncthreads();
        if (more) storeStage();
    }

    // epilogue
#pragma unroll
    for (int mi = 0; mi < 4; mi++) {
        int r0 = row0 + warp_m + mi * 16 + lr;
        int r1 = r0 + 8;
#pragma unroll
        for (int ni = 0; ni < 4; ni++) {
            int cc = col0 + warp_n + ni * 8 + 2 * lc;
            if (r0 < Meff) {
                float v0 = c[mi][ni][0], v1 = c[mi][ni][1];
                if (CMODE == 1) {
                    v0 += Cadd[(size_t)r0 * ldc + cc];
                    v1 += Cadd[(size_t)r0 * ldc + cc + 1];
                }
                float* cp = Cp + (size_t)r0 * ldc + cc;
                cp[0] = v0; cp[1] = v1;
            }
            if (r1 < Meff) {
                float v2 = c[mi][ni][2], v3 = c[mi][ni][3];
                if (CMODE == 1) {
                    v2 += Cadd[(size_t)r1 * ldc + cc];
                    v3 += Cadd[(size_t)r1 * ldc + cc + 1];
                }
                float* cp = Cp + (size_t)r1 * ldc + cc;
                cp[0] = v2; cp[1] = v3;
            }
        }
    }
}

// ---------------- host orchestration ----------------
extern "C" void kernel_launch(void* const* d_in, const int* in_sizes, int n_in,
                              void* d_out, int out_size) {
    const float* x     = (const float*)d_in[0];
    const float* rope  = (const float*)d_in[2];
    const float* w_qkv = (const float*)d_in[4];
    const float* w_o   = (const float*)d_in[5];
    const float* n1    = (const float*)d_in[6];
    const float* n2    = (const float*)d_in[7];
    const float* rw    = (const float*)d_in[8];
    const float* wgu   = (const float*)d_in[9];
    const float* wdn   = (const float*)d_in[10];
    const float* sg    = (const float*)d_in[11];
    const float* su    = (const float*)d_in[12];
    const float* sd    = (const float*)d_in[13];
    float* out = (float*)d_out;

    float *h, *qkv, *attn, *h1, *gu, *hid, *eo, *sc;
    int *cnt, *idx, *slot;
    cudaGetSymbolAddress((void**)&h,    g_h);
    cudaGetSymbolAddress((void**)&qkv,  g_qkv);
    cudaGetSymbolAddress((void**)&attn, g_attn);
    cudaGetSymbolAddress((void**)&h1,   g_h1);
    cudaGetSymbolAddress((void**)&gu,   g_gu);
    cudaGetSymbolAddress((void**)&hid,  g_hid);
    cudaGetSymbolAddress((void**)&eo,   g_eo);
    cudaGetSymbolAddress((void**)&cnt,  g_cnt);
    cudaGetSymbolAddress((void**)&idx,  g_idx);
    cudaGetSymbolAddress((void**)&sc,   g_sc);
    cudaGetSymbolAddress((void**)&slot, g_slot);

    zero_cnt_kernel<<<1, 32>>>(cnt);

    rmsnorm_kernel<<<Ttok, 256>>>(x, n1, h);

    // qkv = h @ w_qkv  (3xTF32: feeds router logit chain)
    tgemm_kernel<0, 0, 3><<<dim3(QKVW / 128, Ttok / 128), 256>>>(
        h, w_qkv, qkv, nullptr, Ttok, QKVW, Dd, Dd, QKVW, QKVW,
        nullptr, nullptr, nullptr, 0, 0, 0);

    rope_kernel<<<(Ttok * 40 * 32 + 255) / 256, 256>>>(qkv, rope);

    attn_kernel<<<dim3(Ss / 64, Hh, Bb), 64>>>(qkv, attn);

    // h1 = x + attn @ w_o  (3xTF32)
    tgemm_kernel<0, 1, 3><<<dim3(Dd / 128, Ttok / 128), 256>>>(
        attn, w_o, h1, x, Ttok, Dd, Dd, Dd, Dd, Dd,
        nullptr, nullptr, nullptr, 0, 0, 0);

    rmsnorm_kernel<<<Ttok, 256>>>(h1, n2, h);

    router_kernel<<<Ttok, 256>>>(h, rw, cnt, idx, sc, slot);

    // shared expert gate & up (1xTF32)
    tgemm_kernel<0, 0, 1><<<dim3(Ii / 128, Ttok / 128), 256>>>(
        h, sg, gu, nullptr, Ttok, Ii, Dd, Dd, Ii, 2048,
        nullptr, nullptr, nullptr, 0, 0, 0);
    tgemm_kernel<0, 0, 1><<<dim3(Ii / 128, Ttok / 128), 256>>>(
        h, su, gu + 1024, nullptr, Ttok, Ii, Dd, Dd, Ii, 2048,
        nullptr, nullptr, nullptr, 0, 0, 0);
    act_kernel<<<(Ttok * 1024) / 256, 256>>>(gu, hid, nullptr);

    // shared-down -> reuse g_attn as buffer (1xTF32)
    tgemm_kernel<0, 0, 1><<<dim3(Dd / 128, Ttok / 128), 256>>>(
        hid, sd, attn, nullptr, Ttok, Dd, Ii, Ii, Dd, Dd,
        nullptr, nullptr, nullptr, 0, 0, 0);

    // routed experts gate_up (gathered rows, scaled), all 8 experts (1xTF32)
    tgemm_kernel<1, 0, 1><<<dim3(2048 / 128, Ttok / 128, Ee), 256>>>(
        h, wgu, gu, nullptr, Ttok, 2048, Dd, Dd, 2048, 2048,
        idx, sc, cnt, 0, (long)Dd * 2048, (long)Ttok * 2048);

    act_kernel<<<(Ee * Ttok * 1024) / 256, 256>>>(gu, hid, cnt);

    // routed down projections, all 8 experts in parallel -> per-slot rows (1xTF32)
    tgemm_kernel<0, 0, 1><<<dim3(Dd / 128, Ttok / 128, Ee), 256>>>(
        hid, wdn, eo, nullptr, Ttok, Dd, Ii, Ii, Dd, Dd,
        nullptr, nullptr, cnt, (long)Ttok * 1024, (long)Ii * Dd, (long)Ttok * Dd);

    // out = h1 + shared_down + eo[slot0] + eo[slot1]
    add4_kernel<<<(Ttok * Dd / 4) / 256, 256>>>(out, h1, attn, eo, slot);
}

// round 5
// speedup vs baseline: 1.8990x; 1.0339x over previous
#include <cuda_runtime.h>
#include <math.h>
#include <stdint.h>

// ---------------- problem constants ----------------
constexpr int Bb   = 2;
constexpr int Ss   = 1024;
constexpr int Dd   = 2048;
constexpr int Hh   = 32;
constexpr int HKV  = 8;
constexpr int HDh  = 64;
constexpr int Ee   = 8;
constexpr int Ii   = 1024;
constexpr int Ttok = Bb * Ss;                 // 2048 tokens
constexpr int QKVW = (Hh + 2 * HKV) * HDh;    // 3072
constexpr int KOFF = Hh * HDh;                // 2048
constexpr int VOFF = (Hh + HKV) * HDh;        // 2560

// ---------------- scratch ----------------
__device__ float g_h   [(size_t)Ttok * Dd];
__device__ float g_qkv [(size_t)Ttok * QKVW];
__device__ float g_attn[(size_t)Ttok * Dd];
__device__ float g_h1  [(size_t)Ttok * Dd];
__device__ float g_gu  [(size_t)Ee * Ttok * 2048];
__device__ float g_hid [(size_t)Ee * Ttok * 1024];
__device__ float g_eo  [(size_t)Ee * Ttok * Dd];
__device__ int   g_cnt [Ee];
__device__ int   g_idx [Ee * Ttok];
__device__ float g_sc  [Ee * Ttok];
__device__ int   g_slot[Ttok * 2];

// ---------------- helpers ----------------
__device__ __forceinline__ uint32_t f2tf(float x) {
    uint32_t u;
    asm("cvt.rna.tf32.f32 %0, %1;" : "=r"(u) : "f"(x));
    return u;
}

__device__ __forceinline__ void mma_tf32(float c[4], uint32_t a0, uint32_t a1,
                                         uint32_t a2, uint32_t a3,
                                         uint32_t b0, uint32_t b1) {
    asm volatile(
        "mma.sync.aligned.m16n8k8.row.col.f32.tf32.tf32.f32 "
        "{%0,%1,%2,%3}, {%4,%5,%6,%7}, {%8,%9}, {%0,%1,%2,%3};"
        : "+f"(c[0]), "+f"(c[1]), "+f"(c[2]), "+f"(c[3])
        : "r"(a0), "r"(a1), "r"(a2), "r"(a3), "r"(b0), "r"(b1));
}

// ---------------- small kernels ----------------
__global__ void zero_cnt_kernel(int* cnt) {
    if (threadIdx.x < Ee) cnt[threadIdx.x] = 0;
}

__global__ void rmsnorm_kernel(const float* __restrict__ x, const float* __restrict__ w,
                               float* __restrict__ out) {
    int row = blockIdx.x;
    const float* xr = x + (size_t)row * Dd;
    float ss = 0.f;
    for (int i = threadIdx.x; i < Dd; i += 256) { float v = xr[i]; ss += v * v; }
    __shared__ float red[256];
    red[threadIdx.x] = ss; __syncthreads();
    for (int s = 128; s > 0; s >>= 1) {
        if (threadIdx.x < s) red[threadIdx.x] += red[threadIdx.x + s];
        __syncthreads();
    }
    float inv = rsqrtf(red[0] / (float)Dd + 1e-5f);
    float* orow = out + (size_t)row * Dd;
    for (int i = threadIdx.x; i < Dd; i += 256) orow[i] = xr[i] * inv * w[i];
}

__global__ void rope_kernel(float* __restrict__ qkv, const float* __restrict__ cache) {
    int idx = blockIdx.x * blockDim.x + threadIdx.x;
    const int TOT = Ttok * 40 * 32;
    if (idx >= TOT) return;
    int p  = idx & 31;
    int hh = (idx >> 5) % 40;
    int t  = idx / (32 * 40);
    int s  = t % Ss;
    float c  = cache[((size_t)s * 32 + p) * 2 + 0];
    float sn = cache[((size_t)s * 32 + p) * 2 + 1];
    float* base = qkv + (size_t)t * QKVW + hh * 64 + 2 * p;
    float x0 = base[0], x1 = base[1];
    base[0] = x0 * c - x1 * sn;
    base[1] = x1 * c + x0 * sn;
}

// flash attention: grid (S/64, H, B), 64 threads; thread = one query row
__global__ __launch_bounds__(64)
void attn_kernel(const float* __restrict__ qkv, float* __restrict__ out) {
    int qt = blockIdx.x, h = blockIdx.y, b = blockIdx.z;
    int tid = threadIdx.x;
    int qi = qt * 64 + tid;
    int t  = b * Ss + qi;
    int kvh = h >> 2;

    const float* qrow = qkv + (size_t)t * QKVW + h * 64;
    float q[64], acc[64];
#pragma unroll
    for (int d = 0; d < 64; d++) { q[d] = qrow[d]; acc[d] = 0.f; }
    float m = -1e30f, l = 0.f;

    __shared__ float Ks[64][64];
    __shared__ float Vs[64][64];

    int ktiles = qt + 1;
    for (int kt = 0; kt < ktiles; kt++) {
        const float* krow = qkv + (size_t)(b * Ss + kt * 64 + tid) * QKVW + KOFF + kvh * 64;
        const float* vrow = qkv + (size_t)(b * Ss + kt * 64 + tid) * QKVW + VOFF + kvh * 64;
#pragma unroll 8
        for (int d = 0; d < 64; d++) { Ks[tid][d] = krow[d]; Vs[tid][d] = vrow[d]; }
        __syncthreads();
        int kmax = qi - kt * 64 + 1;
        if (kmax > 64) kmax = 64;
        for (int k = 0; k < kmax; k++) {
            float s0 = 0.f, s1 = 0.f, s2 = 0.f, s3 = 0.f;
#pragma unroll
            for (int d = 0; d < 64; d += 4) {
                s0 += q[d + 0] * Ks[k][d + 0];
                s1 += q[d + 1] * Ks[k][d + 1];
                s2 += q[d + 2] * Ks[k][d + 2];
                s3 += q[d + 3] * Ks[k][d + 3];
            }
            float s = ((s0 + s1) + (s2 + s3)) * 0.125f;
            if (s > m) {
                float scale = __expf(m - s);
                l *= scale;
#pragma unroll
                for (int d = 0; d < 64; d++) acc[d] *= scale;
                m = s;
            }
            float p = __expf(s - m);
            l += p;
#pragma unroll
            for (int d = 0; d < 64; d++) acc[d] += p * Vs[k][d];
        }
        __syncthreads();
    }
    float invl = 1.f / l;
    float* o = out + (size_t)t * Dd + h * 64;
#pragma unroll
    for (int d = 0; d < 64; d++) o[d] = acc[d] * invl;
}

__global__ void router_kernel(const float* __restrict__ g, const float* __restrict__ rw,
                              int* __restrict__ cnt, int* __restrict__ idx,
                              float* __restrict__ sc, int* __restrict__ slot) {
    int t = blockIdx.x;
    int warp = threadIdx.x >> 5, lane = threadIdx.x & 31;
    const float* gr = g + (size_t)t * Dd;
    float acc = 0.f;
    for (int d = lane; d < Dd; d += 32) acc += gr[d] * rw[(size_t)d * Ee + warp];
    for (int o = 16; o; o >>= 1) acc += __shfl_xor_sync(0xffffffffu, acc, o);
    __shared__ float lg[Ee];
    if (lane == 0) lg[warp] = acc;
    __syncthreads();
    if (threadIdx.x == 0) {
        int b1 = 0;
        for (int e = 1; e < Ee; e++) if (lg[e] > lg[b1]) b1 = e;
        int b2 = -1;
        for (int e = 0; e < Ee; e++) {
            if (e == b1) continue;
            if (b2 < 0 || lg[e] > lg[b2]) b2 = e;
        }
        int p1 = atomicAdd(&cnt[b1], 1);
        idx[b1 * Ttok + p1] = t;
        sc [b1 * Ttok + p1] = 1.f / (1.f + expf(-lg[b1]));
        slot[t * 2 + 0] = b1 * Ttok + p1;
        int p2 = atomicAdd(&cnt[b2], 1);
        idx[b2 * Ttok + p2] = t;
        sc [b2 * Ttok + p2] = 1.f / (1.f + expf(-lg[b2]));
        slot[t * 2 + 1] = b2 * Ttok + p2;
    }
}

__global__ void act_kernel(const float* __restrict__ gu, float* __restrict__ hid,
                           const int* __restrict__ cnt) {
    long gidx = (long)blockIdx.x * 256 + threadIdx.x;
    int e = (int)(gidx / ((long)Ttok * 1024));
    long rem = gidx % ((long)Ttok * 1024);
    int m = (int)(rem >> 10);
    int i = (int)(rem & 1023);
    int Meff = cnt ? cnt[e] : Ttok;
    if (m >= Meff) return;
    const float* gup = gu + (size_t)e * Ttok * 2048 + (size_t)m * 2048;
    float gate = gup[i], up = gup[1024 + i];
    hid[(size_t)e * Ttok * 1024 + (size_t)m * 1024 + i] = gate / (1.f + expf(-gate)) * up;
}

__global__ void add4_kernel(float* __restrict__ out, const float* __restrict__ h1,
                            const float* __restrict__ shd, const float* __restrict__ eo,
                            const int* __restrict__ slot) {
    int gid = blockIdx.x * 256 + threadIdx.x;
    int t = gid / (Dd / 4);
    int d4 = gid % (Dd / 4);
    size_t off = (size_t)t * Dd + d4 * 4;
    int s0 = slot[t * 2 + 0], s1 = slot[t * 2 + 1];
    float4 a = *(const float4*)(h1 + off);
    float4 b = *(const float4*)(shd + off);
    float4 c0 = *(const float4*)(eo + (size_t)s0 * Dd + d4 * 4);
    float4 c1 = *(const float4*)(eo + (size_t)s1 * Dd + d4 * 4);
    float4 r;
    r.x = a.x + b.x + c0.x + c1.x;
    r.y = a.y + b.y + c0.y + c1.y;
    r.z = a.z + b.z + c0.z + c1.z;
    r.w = a.w + b.w + c0.w + c1.w;
    *(float4*)(out + off) = r;
}

// ---------------- tf32 GEMM: 128x128 CTA, 4 warps of 64x64, double-buffered smem ----
// PREC=3: 3xTF32 (fp32-accurate); PREC=1: plain tf32
// CMODE: 0 C=AB ; 1 C=AB+Cadd
constexpr int KSTR = 136;            // smem row stride (u32)
constexpr int STG  = 16 * KSTR;      // u32 per array per stage

template<int GATHER_A, int CMODE, int PREC>
__global__ __launch_bounds__(128, 2)
void tgemm_kernel(const float* __restrict__ A, const float* __restrict__ Bm,
                  float* __restrict__ C, const float* __restrict__ Cadd,
                  int M, int N, int K, int lda, int ldb, int ldc,
                  const int* __restrict__ rowIdx, const float* __restrict__ rowScale,
                  const int* __restrict__ cntPtr,
                  long eAstride, long eBstride, long eCstride) {
    int e = blockIdx.z;
    int Meff = cntPtr ? cntPtr[e] : M;
    int row0 = blockIdx.y * 128, col0 = blockIdx.x * 128;
    if (row0 >= Meff) return;

    constexpr bool LO = (PREC == 3);
    extern __shared__ uint32_t dsm[];
    const int perStage = (LO ? 4 : 2) * STG;

    const int*   rI = rowIdx   ? rowIdx   + (size_t)e * Ttok : nullptr;
    const float* rS = rowScale ? rowScale + (size_t)e * Ttok : nullptr;
    const float* Ap = A  + (size_t)e * eAstride;
    const float* Bp = Bm + (size_t)e * eBstride;
    float*       Cp = C  + (size_t)e * eCstride;

    int tid  = threadIdx.x;
    int lane = tid & 31;
    int wid  = tid >> 5;                 // 0..3
    int warp_m = (wid & 1) * 64;
    int warp_n = (wid >> 1) * 64;
    int lr = lane >> 2, lc = lane & 3;

    // A loader: thread owns row tid, 16 consecutive k
    int a_row = tid;
    int gm = row0 + a_row;
    bool avalid = (gm < Meff);
    const float* arow = Ap;
    float ascale = 1.f;
    if (avalid) {
        int src = GATHER_A ? rI[gm] : gm;
        arow = Ap + (size_t)src * lda;
        if (GATHER_A) ascale = rS[gm];
    }
    // B loader: thread owns k-row tid>>3, 16 consecutive n
    int b_k  = tid >> 3;
    int b_n0 = (tid & 7) * 16;

    float c[4][8][4];
#pragma unroll
    for (int mi = 0; mi < 4; mi++)
#pragma unroll
        for (int ni = 0; ni < 8; ni++)
#pragma unroll
            for (int r = 0; r < 4; r++) c[mi][ni][r] = 0.f;

    float aR[16], bR[16];

    auto loadStage = [&](int k0) {
#pragma unroll
        for (int j = 0; j < 4; j++) {
            float4 v = avalid ? *(const float4*)(arow + k0 + j * 4)
                              : make_float4(0.f, 0.f, 0.f, 0.f);
            aR[j * 4 + 0] = v.x * ascale; aR[j * 4 + 1] = v.y * ascale;
            aR[j * 4 + 2] = v.z * ascale; aR[j * 4 + 3] = v.w * ascale;
        }
        const float* brow = Bp + (size_t)(k0 + b_k) * ldb + col0 + b_n0;
#pragma unroll
        for (int j = 0; j < 4; j++) {
            float4 v = *(const float4*)(brow + j * 4);
            bR[j * 4 + 0] = v.x; bR[j * 4 + 1] = v.y;
            bR[j * 4 + 2] = v.z; bR[j * 4 + 3] = v.w;
        }
    };

    auto storeStage = [&](int s) {
        uint32_t* AsH = dsm + s * perStage;
        uint32_t* BsH = AsH + STG;
        uint32_t* AsL = BsH + STG;
        uint32_t* BsL = AsL + STG;
#pragma unroll
        for (int i = 0; i < 16; i++) {
            uint32_t hi = f2tf(aR[i]);
            AsH[i * KSTR + a_row] = hi;
            if (LO) AsL[i * KSTR + a_row] = f2tf(aR[i] - __uint_as_float(hi));
        }
#pragma unroll
        for (int q = 0; q < 4; q++) {
            uint4 h4;
            h4.x = f2tf(bR[q * 4 + 0]); h4.y = f2tf(bR[q * 4 + 1]);
            h4.z = f2tf(bR[q * 4 + 2]); h4.w = f2tf(bR[q * 4 + 3]);
            *(uint4*)&BsH[b_k * KSTR + b_n0 + q * 4] = h4;
            if (LO) {
                uint4 l4;
                l4.x = f2tf(bR[q * 4 + 0] - __uint_as_float(h4.x));
                l4.y = f2tf(bR[q * 4 + 1] - __uint_as_float(h4.y));
                l4.z = f2tf(bR[q * 4 + 2] - __uint_as_float(h4.z));
                l4.w = f2tf(bR[q * 4 + 3] - __uint_as_float(h4.w));
                *(uint4*)&BsL[b_k * KSTR + b_n0 + q * 4] = l4;
            }
        }
    };

    int nk = K >> 4;
    loadStage(0);
    storeStage(0);

    for (int kt = 0; kt < nk; kt++) {
        __syncthreads();
        bool more = (kt + 1) < nk;
        if (more) loadStage((kt + 1) << 4);

        int s = kt & 1;
        uint32_t* AsH = dsm + s * perStage;
        uint32_t* BsH = AsH + STG;
        uint32_t* AsL = BsH + STG;
        uint32_t* BsL = AsL + STG;

#pragma unroll
        for (int ks = 0; ks < 2; ks++) {
            int kb = ks * 8;
            uint32_t aH[4][4], aL[4][4];
#pragma unroll
            for (int mi = 0; mi < 4; mi++) {
                int r = warp_m + mi * 16 + lr;
                aH[mi][0] = AsH[(kb + lc) * KSTR + r];
                aH[mi][1] = AsH[(kb + lc) * KSTR + r + 8];
                aH[mi][2] = AsH[(kb + lc + 4) * KSTR + r];
                aH[mi][3] = AsH[(kb + lc + 4) * KSTR + r + 8];
                if (LO) {
                    aL[mi][0] = AsL[(kb + lc) * KSTR + r];
                    aL[mi][1] = AsL[(kb + lc) * KSTR + r + 8];
                    aL[mi][2] = AsL[(kb + lc + 4) * KSTR + r];
                    aL[mi][3] = AsL[(kb + lc + 4) * KSTR + r + 8];
                }
            }
#pragma unroll
            for (int ni = 0; ni < 8; ni++) {
                int cn = warp_n + ni * 8 + lr;
                uint32_t b0 = BsH[(kb + lc) * KSTR + cn];
                uint32_t b1 = BsH[(kb + lc + 4) * KSTR + cn];
                if (LO) {
                    uint32_t l0 = BsL[(kb + lc) * KSTR + cn];
                    uint32_t l1 = BsL[(kb + lc + 4) * KSTR + cn];
#pragma unroll
                    for (int mi = 0; mi < 4; mi++) {
                        mma_tf32(c[mi][ni], aL[mi][0], aL[mi][1], aL[mi][2], aL[mi][3],
                                 b0, b1);
                        mma_tf32(c[mi][ni], aH[mi][0], aH[mi][1], aH[mi][2], aH[mi][3],
                                 l0, l1);
                        mma_tf32(c[mi][ni], aH[mi][0], aH[mi][1], aH[mi][2], aH[mi][3],
                                 b0, b1);
                    }
                } else {
#pragma unroll
                    for (int mi = 0; mi < 4; mi++)
                        mma_tf32(c[mi][ni], aH[mi][0], aH[mi][1], aH[mi][2], aH[mi][3],
                                 b0, b1);
                }
            }
        }
        if (more) storeStage((kt + 1) & 1);
    }

    // epilogue
#pragma unroll
    for (int mi = 0; mi < 4; mi++) {
        int r0 = row0 + warp_m + mi * 16 + lr;
        int r1 = r0 + 8;
#pragma unroll
        for (int ni = 0; ni < 8; ni++) {
            int cc = col0 + warp_n + ni * 8 + 2 * lc;
            if (r0 < Meff) {
                float v0 = c[mi][ni][0], v1 = c[mi][ni][1];
                if (CMODE == 1) {
                    v0 += Cadd[(size_t)r0 * ldc + cc];
                    v1 += Cadd[(size_t)r0 * ldc + cc + 1];
                }
                float* cp = Cp + (size_t)r0 * ldc + cc;
                cp[0] = v0; cp[1] = v1;
            }
            if (r1 < Meff) {
                float v2 = c[mi][ni][2], v3 = c[mi][ni][3];
                if (CMODE == 1) {
                    v2 += Cadd[(size_t)r1 * ldc + cc];
                    v3 += Cadd[(size_t)r1 * ldc + cc + 1];
                }
                float* cp = Cp + (size_t)r1 * ldc + cc;
                cp[0] = v2; cp[1] = v3;
            }
        }
    }
}

// ---------------- host orchestration ----------------
extern "C" void kernel_launch(void* const* d_in, const int* in_sizes, int n_in,
                              void* d_out, int out_size) {
    const float* x     = (const float*)d_in[0];
    const float* rope  = (const float*)d_in[2];
    const float* w_qkv = (const float*)d_in[4];
    const float* w_o   = (const float*)d_in[5];
    const float* n1    = (const float*)d_in[6];
    const float* n2    = (const float*)d_in[7];
    const float* rw    = (const float*)d_in[8];
    const float* wgu   = (const float*)d_in[9];
    const float* wdn   = (const float*)d_in[10];
    const float* sg    = (const float*)d_in[11];
    const float* su    = (const float*)d_in[12];
    const float* sd    = (const float*)d_in[13];
    float* out = (float*)d_out;

    float *h, *qkv, *attn, *h1, *gu, *hid, *eo, *sc;
    int *cnt, *idx, *slot;
    cudaGetSymbolAddress((void**)&h,    g_h);
    cudaGetSymbolAddress((void**)&qkv,  g_qkv);
    cudaGetSymbolAddress((void**)&attn, g_attn);
    cudaGetSymbolAddress((void**)&h1,   g_h1);
    cudaGetSymbolAddress((void**)&gu,   g_gu);
    cudaGetSymbolAddress((void**)&hid,  g_hid);
    cudaGetSymbolAddress((void**)&eo,   g_eo);
    cudaGetSymbolAddress((void**)&cnt,  g_cnt);
    cudaGetSymbolAddress((void**)&idx,  g_idx);
    cudaGetSymbolAddress((void**)&sc,   g_sc);
    cudaGetSymbolAddress((void**)&slot, g_slot);

    const int SM1 = 2 * 2 * STG * 4;          // 34816 B (PREC=1, 2 stages)
    const int SM3 = 2 * 4 * STG * 4;          // 69632 B (PREC=3, 2 stages)
    cudaFuncSetAttribute(tgemm_kernel<0, 0, 3>,
                         cudaFuncAttributeMaxDynamicSharedMemorySize, SM3);
    cudaFuncSetAttribute(tgemm_kernel<0, 1, 3>,
                         cudaFuncAttributeMaxDynamicSharedMemorySize, SM3);
    cudaFuncSetAttribute(tgemm_kernel<0, 0, 1>,
                         cudaFuncAttributeMaxDynamicSharedMemorySize, SM1);
    cudaFuncSetAttribute(tgemm_kernel<1, 0, 1>,
                         cudaFuncAttributeMaxDynamicSharedMemorySize, SM1);

    zero_cnt_kernel<<<1, 32>>>(cnt);

    rmsnorm_kernel<<<Ttok, 256>>>(x, n1, h);

    // qkv = h @ w_qkv  (3xTF32)
    tgemm_kernel<0, 0, 3><<<dim3(QKVW / 128, Ttok / 128), 128, SM3>>>(
        h, w_qkv, qkv, nullptr, Ttok, QKVW, Dd, Dd, QKVW, QKVW,
        nullptr, nullptr, nullptr, 0, 0, 0);

    rope_kernel<<<(Ttok * 40 * 32 + 255) / 256, 256>>>(qkv, rope);

    attn_kernel<<<dim3(Ss / 64, Hh, Bb), 64>>>(qkv, attn);

    // h1 = x + attn @ w_o  (3xTF32)
    tgemm_kernel<0, 1, 3><<<dim3(Dd / 128, Ttok / 128), 128, SM3>>>(
        attn, w_o, h1, x, Ttok, Dd, Dd, Dd, Dd, Dd,
        nullptr, nullptr, nullptr, 0, 0, 0);

    rmsnorm_kernel<<<Ttok, 256>>>(h1, n2, h);

    router_kernel<<<Ttok, 256>>>(h, rw, cnt, idx, sc, slot);

    // shared expert gate & up (1xTF32)
    tgemm_kernel<0, 0, 1><<<dim3(Ii / 128, Ttok / 128), 128, SM1>>>(
        h, sg, gu, nullptr, Ttok, Ii, Dd, Dd, Ii, 2048,
        nullptr, nullptr, nullptr, 0, 0, 0);
    tgemm_kernel<0, 0, 1><<<dim3(Ii / 128, Ttok / 128), 128, SM1>>>(
        h, su, gu + 1024, nullptr, Ttok, Ii, Dd, Dd, Ii, 2048,
        nullptr, nullptr, nullptr, 0, 0, 0);
    act_kernel<<<(Ttok * 1024) / 256, 256>>>(gu, hid, nullptr);

    // shared-down -> reuse g_attn (1xTF32)
    tgemm_kernel<0, 0, 1><<<dim3(Dd / 128, Ttok / 128), 128, SM1>>>(
        hid, sd, attn, nullptr, Ttok, Dd, Ii, Ii, Dd, Dd,
        nullptr, nullptr, nullptr, 0, 0, 0);

    // routed experts gate_up (1xTF32), all 8 experts
    tgemm_kernel<1, 0, 1><<<dim3(2048 / 128, Ttok / 128, Ee), 128, SM1>>>(
        h, wgu, gu, nullptr, Ttok, 2048, Dd, Dd, 2048, 2048,
        idx, sc, cnt, 0, (long)Dd * 2048, (long)Ttok * 2048);

    act_kernel<<<(Ee * Ttok * 1024) / 256, 256>>>(gu, hid, cnt);

    // routed down projections (1xTF32), all 8 experts -> per-slot rows
    tgemm_kernel<0, 0, 1><<<dim3(Dd / 128, Ttok / 128, Ee), 128, SM1>>>(
        hid, wdn, eo, nullptr, Ttok, Dd, Ii, Ii, Dd, Dd,
        nullptr, nullptr, cnt, (long)Ttok * 1024, (long)Ii * Dd, (long)Ttok * Dd);

    // out = h1 + shared_down + eo[slot0] + eo[slot1]
    add4_kernel<<<(Ttok * Dd / 4) / 256, 256>>>(out, h1, attn, eo, slot);
}

// round 6
// speedup vs baseline: 2.1371x; 1.1254x over previous
#include <cuda_runtime.h>
#include <cuda_bf16.h>
#include <math.h>
#include <stdint.h>

// ---------------- problem constants ----------------
constexpr int Bb   = 2;
constexpr int Ss   = 1024;
constexpr int Dd   = 2048;
constexpr int Hh   = 32;
constexpr int HKV  = 8;
constexpr int HDh  = 64;
constexpr int Ee   = 8;
constexpr int Ii   = 1024;
constexpr int Ttok = Bb * Ss;                 // 2048 tokens
constexpr int QKVW = (Hh + 2 * HKV) * HDh;    // 3072
constexpr int KOFF = Hh * HDh;                // 2048
constexpr int VOFF = (Hh + HKV) * HDh;        // 2560

// ---------------- scratch ----------------
__device__ float g_h   [(size_t)Ttok * Dd];
__device__ float g_qkv [(size_t)Ttok * QKVW];
__device__ float g_attn[(size_t)Ttok * Dd];
__device__ float g_h1  [(size_t)Ttok * Dd];
__device__ float g_gu  [(size_t)Ee * Ttok * 2048];
__device__ float g_hid [(size_t)Ee * Ttok * 1024];
__device__ float g_eo  [(size_t)Ee * Ttok * Dd];
__device__ int   g_cnt [Ee];
__device__ int   g_idx [Ee * Ttok];
__device__ float g_sc  [Ee * Ttok];
__device__ int   g_slot[Ttok * 2];

// ---------------- helpers ----------------
__device__ __forceinline__ uint32_t f2tf(float x) {
    uint32_t u;
    asm("cvt.rna.tf32.f32 %0, %1;" : "=r"(u) : "f"(x));
    return u;
}

__device__ __forceinline__ void mma_tf32(float c[4], uint32_t a0, uint32_t a1,
                                         uint32_t a2, uint32_t a3,
                                         uint32_t b0, uint32_t b1) {
    asm volatile(
        "mma.sync.aligned.m16n8k8.row.col.f32.tf32.tf32.f32 "
        "{%0,%1,%2,%3}, {%4,%5,%6,%7}, {%8,%9}, {%0,%1,%2,%3};"
        : "+f"(c[0]), "+f"(c[1]), "+f"(c[2]), "+f"(c[3])
        : "r"(a0), "r"(a1), "r"(a2), "r"(a3), "r"(b0), "r"(b1));
}

__device__ __forceinline__ void mma_bf16(float c[4], uint32_t a0, uint32_t a1,
                                         uint32_t a2, uint32_t a3,
                                         uint32_t b0, uint32_t b1) {
    asm volatile(
        "mma.sync.aligned.m16n8k16.row.col.f32.bf16.bf16.f32 "
        "{%0,%1,%2,%3}, {%4,%5,%6,%7}, {%8,%9}, {%0,%1,%2,%3};"
        : "+f"(c[0]), "+f"(c[1]), "+f"(c[2]), "+f"(c[3])
        : "r"(a0), "r"(a1), "r"(a2), "r"(a3), "r"(b0), "r"(b1));
}

// split (x,y) into packed bf16x2 hi and lo (residual) words; low 16 bits = x
__device__ __forceinline__ void bf_split2(float x, float y, uint32_t& hi, uint32_t& lo) {
    __nv_bfloat16 hx = __float2bfloat16_rn(x);
    __nv_bfloat16 hy = __float2bfloat16_rn(y);
    float rx = x - __bfloat162float(hx);
    float ry = y - __bfloat162float(hy);
    __nv_bfloat16 lx = __float2bfloat16_rn(rx);
    __nv_bfloat16 ly = __float2bfloat16_rn(ry);
    hi = (uint32_t)__bfloat16_as_ushort(hx) | ((uint32_t)__bfloat16_as_ushort(hy) << 16);
    lo = (uint32_t)__bfloat16_as_ushort(lx) | ((uint32_t)__bfloat16_as_ushort(ly) << 16);
}

// ---------------- small kernels ----------------
__global__ void zero_cnt_kernel(int* cnt) {
    if (threadIdx.x < Ee) cnt[threadIdx.x] = 0;
}

__global__ void rmsnorm_kernel(const float* __restrict__ x, const float* __restrict__ w,
                               float* __restrict__ out) {
    int row = blockIdx.x;
    const float* xr = x + (size_t)row * Dd;
    float ss = 0.f;
    for (int i = threadIdx.x; i < Dd; i += 256) { float v = xr[i]; ss += v * v; }
    __shared__ float red[256];
    red[threadIdx.x] = ss; __syncthreads();
    for (int s = 128; s > 0; s >>= 1) {
        if (threadIdx.x < s) red[threadIdx.x] += red[threadIdx.x + s];
        __syncthreads();
    }
    float inv = rsqrtf(red[0] / (float)Dd + 1e-5f);
    float* orow = out + (size_t)row * Dd;
    for (int i = threadIdx.x; i < Dd; i += 256) orow[i] = xr[i] * inv * w[i];
}

__global__ void rope_kernel(float* __restrict__ qkv, const float* __restrict__ cache) {
    int idx = blockIdx.x * blockDim.x + threadIdx.x;
    const int TOT = Ttok * 40 * 32;
    if (idx >= TOT) return;
    int p  = idx & 31;
    int hh = (idx >> 5) % 40;
    int t  = idx / (32 * 40);
    int s  = t % Ss;
    float c  = cache[((size_t)s * 32 + p) * 2 + 0];
    float sn = cache[((size_t)s * 32 + p) * 2 + 1];
    float* base = qkv + (size_t)t * QKVW + hh * 64 + 2 * p;
    float x0 = base[0], x1 = base[1];
    base[0] = x0 * c - x1 * sn;
    base[1] = x1 * c + x0 * sn;
}

// flash attention: grid (S/64, H, B), 64 threads; thread = one query row
__global__ __launch_bounds__(64)
void attn_kernel(const float* __restrict__ qkv, float* __restrict__ out) {
    int qt = blockIdx.x, h = blockIdx.y, b = blockIdx.z;
    int tid = threadIdx.x;
    int qi = qt * 64 + tid;
    int t  = b * Ss + qi;
    int kvh = h >> 2;

    const float* qrow = qkv + (size_t)t * QKVW + h * 64;
    float q[64], acc[64];
#pragma unroll
    for (int d = 0; d < 64; d++) { q[d] = qrow[d]; acc[d] = 0.f; }
    float m = -1e30f, l = 0.f;

    __shared__ float Ks[64][64];
    __shared__ float Vs[64][64];

    int ktiles = qt + 1;
    for (int kt = 0; kt < ktiles; kt++) {
        const float* krow = qkv + (size_t)(b * Ss + kt * 64 + tid) * QKVW + KOFF + kvh * 64;
        const float* vrow = qkv + (size_t)(b * Ss + kt * 64 + tid) * QKVW + VOFF + kvh * 64;
#pragma unroll 8
        for (int d = 0; d < 64; d++) { Ks[tid][d] = krow[d]; Vs[tid][d] = vrow[d]; }
        __syncthreads();
        int kmax = qi - kt * 64 + 1;
        if (kmax > 64) kmax = 64;
        for (int k = 0; k < kmax; k++) {
            float s0 = 0.f, s1 = 0.f, s2 = 0.f, s3 = 0.f;
#pragma unroll
            for (int d = 0; d < 64; d += 4) {
                s0 += q[d + 0] * Ks[k][d + 0];
                s1 += q[d + 1] * Ks[k][d + 1];
                s2 += q[d + 2] * Ks[k][d + 2];
                s3 += q[d + 3] * Ks[k][d + 3];
            }
            float s = ((s0 + s1) + (s2 + s3)) * 0.125f;
            if (s > m) {
                float scale = __expf(m - s);
                l *= scale;
#pragma unroll
                for (int d = 0; d < 64; d++) acc[d] *= scale;
                m = s;
            }
            float p = __expf(s - m);
            l += p;
#pragma unroll
            for (int d = 0; d < 64; d++) acc[d] += p * Vs[k][d];
        }
        __syncthreads();
    }
    float invl = 1.f / l;
    float* o = out + (size_t)t * Dd + h * 64;
#pragma unroll
    for (int d = 0; d < 64; d++) o[d] = acc[d] * invl;
}

__global__ void router_kernel(const float* __restrict__ g, const float* __restrict__ rw,
                              int* __restrict__ cnt, int* __restrict__ idx,
                              float* __restrict__ sc, int* __restrict__ slot) {
    int t = blockIdx.x;
    int warp = threadIdx.x >> 5, lane = threadIdx.x & 31;
    const float* gr = g + (size_t)t * Dd;
    float acc = 0.f;
    for (int d = lane; d < Dd; d += 32) acc += gr[d] * rw[(size_t)d * Ee + warp];
    for (int o = 16; o; o >>= 1) acc += __shfl_xor_sync(0xffffffffu, acc, o);
    __shared__ float lg[Ee];
    if (lane == 0) lg[warp] = acc;
    __syncthreads();
    if (threadIdx.x == 0) {
        int b1 = 0;
        for (int e = 1; e < Ee; e++) if (lg[e] > lg[b1]) b1 = e;
        int b2 = -1;
        for (int e = 0; e < Ee; e++) {
            if (e == b1) continue;
            if (b2 < 0 || lg[e] > lg[b2]) b2 = e;
        }
        int p1 = atomicAdd(&cnt[b1], 1);
        idx[b1 * Ttok + p1] = t;
        sc [b1 * Ttok + p1] = 1.f / (1.f + expf(-lg[b1]));
        slot[t * 2 + 0] = b1 * Ttok + p1;
        int p2 = atomicAdd(&cnt[b2], 1);
        idx[b2 * Ttok + p2] = t;
        sc [b2 * Ttok + p2] = 1.f / (1.f + expf(-lg[b2]));
        slot[t * 2 + 1] = b2 * Ttok + p2;
    }
}

__global__ void act_kernel(const float* __restrict__ gu, float* __restrict__ hid,
                           const int* __restrict__ cnt) {
    long gidx = (long)blockIdx.x * 256 + threadIdx.x;
    int e = (int)(gidx / ((long)Ttok * 1024));
    long rem = gidx % ((long)Ttok * 1024);
    int m = (int)(rem >> 10);
    int i = (int)(rem & 1023);
    int Meff = cnt ? cnt[e] : Ttok;
    if (m >= Meff) return;
    const float* gup = gu + (size_t)e * Ttok * 2048 + (size_t)m * 2048;
    float gate = gup[i], up = gup[1024 + i];
    hid[(size_t)e * Ttok * 1024 + (size_t)m * 1024 + i] = gate / (1.f + expf(-gate)) * up;
}

__global__ void add4_kernel(float* __restrict__ out, const float* __restrict__ h1,
                            const float* __restrict__ shd, const float* __restrict__ eo,
                            const int* __restrict__ slot) {
    int gid = blockIdx.x * 256 + threadIdx.x;
    int t = gid / (Dd / 4);
    int d4 = gid % (Dd / 4);
    size_t off = (size_t)t * Dd + d4 * 4;
    int s0 = slot[t * 2 + 0], s1 = slot[t * 2 + 1];
    float4 a = *(const float4*)(h1 + off);
    float4 b = *(const float4*)(shd + off);
    float4 c0 = *(const float4*)(eo + (size_t)s0 * Dd + d4 * 4);
    float4 c1 = *(const float4*)(eo + (size_t)s1 * Dd + d4 * 4);
    float4 r;
    r.x = a.x + b.x + c0.x + c1.x;
    r.y = a.y + b.y + c0.y + c1.y;
    r.z = a.z + b.z + c0.z + c1.z;
    r.w = a.w + b.w + c0.w + c1.w;
    *(float4*)(out + off) = r;
}

// ---------------- tensor-core GEMM: 128x128 CTA, 4 warps of 64x64, double-buffered ----
// PREC=1: tf32 single  | PREC=2: bf16x3 (HH+HL+LH, ~fp23-accurate)
// CMODE: 0 C=AB ; 1 C=AB+Cadd
constexpr int KSTR = 136;                 // smem row stride (u32)

template<int GATHER_A, int CMODE, int PREC>
__global__ __launch_bounds__(128, 2)
void tgemm_kernel(const float* __restrict__ A, const float* __restrict__ Bm,
                  float* __restrict__ C, const float* __restrict__ Cadd,
                  int M, int N, int K, int lda, int ldb, int ldc,
                  const int* __restrict__ rowIdx, const float* __restrict__ rowScale,
                  const int* __restrict__ cntPtr,
                  long eAstride, long eBstride, long eCstride) {
    int e = blockIdx.z;
    int Meff = cntPtr ? cntPtr[e] : M;
    int row0 = blockIdx.y * 128, col0 = blockIdx.x * 128;
    if (row0 >= Meff) return;

    extern __shared__ uint32_t dsm[];
    // PREC1: [AsH 16xKSTR][BsH 16xKSTR]  PREC2: [APH 8][BPH 8][APL 8][BPL 8]
    constexpr int perStage = 2 * 16 * KSTR;       // 4352 u32 both cases

    const int*   rI = rowIdx   ? rowIdx   + (size_t)e * Ttok : nullptr;
    const float* rS = rowScale ? rowScale + (size_t)e * Ttok : nullptr;
    const float* Ap = A  + (size_t)e * eAstride;
    const float* Bp = Bm + (size_t)e * eBstride;
    float*       Cp = C  + (size_t)e * eCstride;

    int tid  = threadIdx.x;
    int lane = tid & 31;
    int wid  = tid >> 5;
    int warp_m = (wid & 1) * 64;
    int warp_n = (wid >> 1) * 64;
    int lr = lane >> 2, lc = lane & 3;

    // A loader: thread owns row tid, 16 consecutive k
    int a_row = tid;
    int gm = row0 + a_row;
    bool avalid = (gm < Meff);
    const float* arow = Ap;
    float ascale = 1.f;
    if (avalid) {
        int src = GATHER_A ? rI[gm] : gm;
        arow = Ap + (size_t)src * lda;
        if (GATHER_A) ascale = rS[gm];
    }
    // B loader (PREC1): k-row tid>>3, 16 cols ; (PREC2): pair-row tid>>4, 8 cols x 2 k-rows
    int b_k  = tid >> 3;
    int b_n0 = (tid & 7) * 16;
    int bp   = tid >> 4;
    int bpn0 = (tid & 15) * 8;

    float c[4][8][4];
#pragma unroll
    for (int mi = 0; mi < 4; mi++)
#pragma unroll
        for (int ni = 0; ni < 8; ni++)
#pragma unroll
            for (int r = 0; r < 4; r++) c[mi][ni][r] = 0.f;

    float aR[16], bR[16];

    auto loadStage = [&](int k0) {
#pragma unroll
        for (int j = 0; j < 4; j++) {
            float4 v = avalid ? *(const float4*)(arow + k0 + j * 4)
                              : make_float4(0.f, 0.f, 0.f, 0.f);
            aR[j * 4 + 0] = v.x * ascale; aR[j * 4 + 1] = v.y * ascale;
            aR[j * 4 + 2] = v.z * ascale; aR[j * 4 + 3] = v.w * ascale;
        }
        if (PREC == 1) {
            const float* brow = Bp + (size_t)(k0 + b_k) * ldb + col0 + b_n0;
#pragma unroll
            for (int j = 0; j < 4; j++) {
                float4 v = *(const float4*)(brow + j * 4);
                bR[j * 4 + 0] = v.x; bR[j * 4 + 1] = v.y;
                bR[j * 4 + 2] = v.z; bR[j * 4 + 3] = v.w;
            }
        } else {
            const float* br0 = Bp + (size_t)(k0 + 2 * bp) * ldb + col0 + bpn0;
            const float* br1 = br0 + ldb;
#pragma unroll
            for (int j = 0; j < 2; j++) {
                float4 v0 = *(const float4*)(br0 + j * 4);
                float4 v1 = *(const float4*)(br1 + j * 4);
                bR[j * 4 + 0] = v0.x; bR[j * 4 + 1] = v0.y;
                bR[j * 4 + 2] = v0.z; bR[j * 4 + 3] = v0.w;
                bR[8 + j * 4 + 0] = v1.x; bR[8 + j * 4 + 1] = v1.y;
                bR[8 + j * 4 + 2] = v1.z; bR[8 + j * 4 + 3] = v1.w;
            }
        }
    };

    auto storeStage = [&](int s) {
        if (PREC == 1) {
            uint32_t* AsH = dsm + s * perStage;
            uint32_t* BsH = AsH + 16 * KSTR;
#pragma unroll
            for (int i = 0; i < 16; i++) AsH[i * KSTR + a_row] = f2tf(aR[i]);
#pragma unroll
            for (int q = 0; q < 4; q++) {
                uint4 h4;
                h4.x = f2tf(bR[q * 4 + 0]); h4.y = f2tf(bR[q * 4 + 1]);
                h4.z = f2tf(bR[q * 4 + 2]); h4.w = f2tf(bR[q * 4 + 3]);
                *(uint4*)&BsH[b_k * KSTR + b_n0 + q * 4] = h4;
            }
        } else {
            uint32_t* APH = dsm + s * perStage;
            uint32_t* BPH = APH + 8 * KSTR;
            uint32_t* APL = BPH + 8 * KSTR;
            uint32_t* BPL = APL + 8 * KSTR;
#pragma unroll
            for (int p = 0; p < 8; p++) {
                uint32_t hi, lo;
                bf_split2(aR[2 * p], aR[2 * p + 1], hi, lo);
                APH[p * KSTR + a_row] = hi;
                APL[p * KSTR + a_row] = lo;
            }
            uint32_t hv[8], lv[8];
#pragma unroll
            for (int j = 0; j < 8; j++) bf_split2(bR[j], bR[8 + j], hv[j], lv[j]);
            *(uint4*)&BPH[bp * KSTR + bpn0]     = make_uint4(hv[0], hv[1], hv[2], hv[3]);
            *(uint4*)&BPH[bp * KSTR + bpn0 + 4] = make_uint4(hv[4], hv[5], hv[6], hv[7]);
            *(uint4*)&BPL[bp * KSTR + bpn0]     = make_uint4(lv[0], lv[1], lv[2], lv[3]);
            *(uint4*)&BPL[bp * KSTR + bpn0 + 4] = make_uint4(lv[4], lv[5], lv[6], lv[7]);
        }
    };

    int nk = K >> 4;
    loadStage(0);
    storeStage(0);

    for (int kt = 0; kt < nk; kt++) {
        __syncthreads();
        bool more = (kt + 1) < nk;
        if (more) loadStage((kt + 1) << 4);

        int s = kt & 1;
        if (PREC == 1) {
            uint32_t* AsH = dsm + s * perStage;
            uint32_t* BsH = AsH + 16 * KSTR;
#pragma unroll
            for (int ks = 0; ks < 2; ks++) {
                int kb = ks * 8;
                uint32_t aH[4][4];
#pragma unroll
                for (int mi = 0; mi < 4; mi++) {
                    int r = warp_m + mi * 16 + lr;
                    aH[mi][0] = AsH[(kb + lc) * KSTR + r];
                    aH[mi][1] = AsH[(kb + lc) * KSTR + r + 8];
                    aH[mi][2] = AsH[(kb + lc + 4) * KSTR + r];
                    aH[mi][3] = AsH[(kb + lc + 4) * KSTR + r + 8];
                }
#pragma unroll
                for (int ni = 0; ni < 8; ni++) {
                    int cn = warp_n + ni * 8 + lr;
                    uint32_t b0 = BsH[(kb + lc) * KSTR + cn];
                    uint32_t b1 = BsH[(kb + lc + 4) * KSTR + cn];
#pragma unroll
                    for (int mi = 0; mi < 4; mi++)
                        mma_tf32(c[mi][ni], aH[mi][0], aH[mi][1], aH[mi][2], aH[mi][3],
                                 b0, b1);
                }
            }
        } else {
            uint32_t* APH = dsm + s * perStage;
            uint32_t* BPH = APH + 8 * KSTR;
            uint32_t* APL = BPH + 8 * KSTR;
            uint32_t* BPL = APL + 8 * KSTR;
            uint32_t aH[4][4], aL[4][4];
#pragma unroll
            for (int mi = 0; mi < 4; mi++) {
                int r = warp_m + mi * 16 + lr;
                aH[mi][0] = APH[lc * KSTR + r];
                aH[mi][1] = APH[lc * KSTR + r + 8];
                aH[mi][2] = APH[(lc + 4) * KSTR + r];
                aH[mi][3] = APH[(lc + 4) * KSTR + r + 8];
                aL[mi][0] = APL[lc * KSTR + r];
                aL[mi][1] = APL[lc * KSTR + r + 8];
                aL[mi][2] = APL[(lc + 4) * KSTR + r];
                aL[mi][3] = APL[(lc + 4) * KSTR + r + 8];
            }
#pragma unroll
            for (int ni = 0; ni < 8; ni++) {
                int cn = warp_n + ni * 8 + lr;
                uint32_t bh0 = BPH[lc * KSTR + cn];
                uint32_t bh1 = BPH[(lc + 4) * KSTR + cn];
                uint32_t bl0 = BPL[lc * KSTR + cn];
                uint32_t bl1 = BPL[(lc + 4) * KSTR + cn];
#pragma unroll
                for (int mi = 0; mi < 4; mi++) {
                    mma_bf16(c[mi][ni], aL[mi][0], aL[mi][1], aL[mi][2], aL[mi][3],
                             bh0, bh1);
                    mma_bf16(c[mi][ni], aH[mi][0], aH[mi][1], aH[mi][2], aH[mi][3],
                             bl0, bl1);
                    mma_bf16(c[mi][ni], aH[mi][0], aH[mi][1], aH[mi][2], aH[mi][3],
                             bh0, bh1);
                }
            }
        }
        if (more) storeStage((kt + 1) & 1);
    }

    // epilogue
#pragma unroll
    for (int mi = 0; mi < 4; mi++) {
        int r0 = row0 + warp_m + mi * 16 + lr;
        int r1 = r0 + 8;
#pragma unroll
        for (int ni = 0; ni < 8; ni++) {
            int cc = col0 + warp_n + ni * 8 + 2 * lc;
            if (r0 < Meff) {
                float v0 = c[mi][ni][0], v1 = c[mi][ni][1];
                if (CMODE == 1) {
                    v0 += Cadd[(size_t)r0 * ldc + cc];
                    v1 += Cadd[(size_t)r0 * ldc + cc + 1];
                }
                float* cp = Cp + (size_t)r0 * ldc + cc;
                cp[0] = v0; cp[1] = v1;
            }
            if (r1 < Meff) {
                float v2 = c[mi][ni][2], v3 = c[mi][ni][3];
                if (CMODE == 1) {
                    v2 += Cadd[(size_t)r1 * ldc + cc];
                    v3 += Cadd[(size_t)r1 * ldc + cc + 1];
                }
                float* cp = Cp + (size_t)r1 * ldc + cc;
                cp[0] = v2; cp[1] = v3;
            }
        }
    }
}

// ---------------- host orchestration ----------------
extern "C" void kernel_launch(void* const* d_in, const int* in_sizes, int n_in,
                              void* d_out, int out_size) {
    const float* x     = (const float*)d_in[0];
    const float* rope  = (const float*)d_in[2];
    const float* w_qkv = (const float*)d_in[4];
    const float* w_o   = (const float*)d_in[5];
    const float* n1    = (const float*)d_in[6];
    const float* n2    = (const float*)d_in[7];
    const float* rw    = (const float*)d_in[8];
    const float* wgu   = (const float*)d_in[9];
    const float* wdn   = (const float*)d_in[10];
    const float* sg    = (const float*)d_in[11];
    const float* su    = (const float*)d_in[12];
    const float* sd    = (const float*)d_in[13];
    float* out = (float*)d_out;

    float *h, *qkv, *attn, *h1, *gu, *hid, *eo, *sc;
    int *cnt, *idx, *slot;
    cudaGetSymbolAddress((void**)&h,    g_h);
    cudaGetSymbolAddress((void**)&qkv,  g_qkv);
    cudaGetSymbolAddress((void**)&attn, g_attn);
    cudaGetSymbolAddress((void**)&h1,   g_h1);
    cudaGetSymbolAddress((void**)&gu,   g_gu);
    cudaGetSymbolAddress((void**)&hid,  g_hid);
    cudaGetSymbolAddress((void**)&eo,   g_eo);
    cudaGetSymbolAddress((void**)&cnt,  g_cnt);
    cudaGetSymbolAddress((void**)&idx,  g_idx);
    cudaGetSymbolAddress((void**)&sc,   g_sc);
    cudaGetSymbolAddress((void**)&slot, g_slot);

    const int SMB = 2 * 2 * 16 * KSTR * 4;    // 34816 B (both PREC variants)

    zero_cnt_kernel<<<1, 32>>>(cnt);

    rmsnorm_kernel<<<Ttok, 256>>>(x, n1, h);

    // qkv = h @ w_qkv  (bf16x3)
    tgemm_kernel<0, 0, 2><<<dim3(QKVW / 128, Ttok / 128), 128, SMB>>>(
        h, w_qkv, qkv, nullptr, Ttok, QKVW, Dd, Dd, QKVW, QKVW,
        nullptr, nullptr, nullptr, 0, 0, 0);

    rope_kernel<<<(Ttok * 40 * 32 + 255) / 256, 256>>>(qkv, rope);

    attn_kernel<<<dim3(Ss / 64, Hh, Bb), 64>>>(qkv, attn);

    // h1 = x + attn @ w_o  (bf16x3)
    tgemm_kernel<0, 1, 2><<<dim3(Dd / 128, Ttok / 128), 128, SMB>>>(
        attn, w_o, h1, x, Ttok, Dd, Dd, Dd, Dd, Dd,
        nullptr, nullptr, nullptr, 0, 0, 0);

    rmsnorm_kernel<<<Ttok, 256>>>(h1, n2, h);

    router_kernel<<<Ttok, 256>>>(h, rw, cnt, idx, sc, slot);

    // shared expert gate & up (tf32x1)
    tgemm_kernel<0, 0, 1><<<dim3(Ii / 128, Ttok / 128), 128, SMB>>>(
        h, sg, gu, nullptr, Ttok, Ii, Dd, Dd, Ii, 2048,
        nullptr, nullptr, nullptr, 0, 0, 0);
    tgemm_kernel<0, 0, 1><<<dim3(Ii / 128, Ttok / 128), 128, SMB>>>(
        h, su, gu + 1024, nullptr, Ttok, Ii, Dd, Dd, Ii, 2048,
        nullptr, nullptr, nullptr, 0, 0, 0);
    act_kernel<<<(Ttok * 1024) / 256, 256>>>(gu, hid, nullptr);

    // shared-down -> reuse g_attn (tf32x1)
    tgemm_kernel<0, 0, 1><<<dim3(Dd / 128, Ttok / 128), 128, SMB>>>(
        hid, sd, attn, nullptr, Ttok, Dd, Ii, Ii, Dd, Dd,
        nullptr, nullptr, nullptr, 0, 0, 0);

    // routed experts gate_up (tf32x1), all 8 experts
    tgemm_kernel<1, 0, 1><<<dim3(2048 / 128, Ttok / 128, Ee), 128, SMB>>>(
        h, wgu, gu, nullptr, Ttok, 2048, Dd, Dd, 2048, 2048,
        idx, sc, cnt, 0, (long)Dd * 2048, (long)Ttok * 2048);

    act_kernel<<<(Ee * Ttok * 1024) / 256, 256>>>(gu, hid, cnt);

    // routed down projections (tf32x1), all 8 experts -> per-slot rows
    tgemm_kernel<0, 0, 1><<<dim3(Dd / 128, Ttok / 128, Ee), 128, SMB>>>(
        hid, wdn, eo, nullptr, Ttok, Dd, Ii, Ii, Dd, Dd,
        nullptr, nullptr, cnt, (long)Ttok * 1024, (long)Ii * Dd, (long)Ttok * Dd);

    // out = h1 + shared_down + eo[slot0] + eo[slot1]
    add4_kernel<<<(Ttok * Dd / 4) / 256, 256>>>(out, h1, attn, eo, slot);
}